// round 14
// baseline (speedup 1.0000x reference)
#include <cuda_runtime.h>
#include <cuda_bf16.h>
#include <cuda_fp16.h>
#include <math.h>
#include <stdint.h>

// Problem constants (fixed by the reference)
#define NN   10000
#define FIN  3000
#define H1D  500
#define H2D  64
#define NE   160000
#define BN_EPS 1e-5f
#define LDH  512           // padded leading dim for K=500 operands (16B-aligned rows)

static inline int cdiv(int a, int b) { return (a + b - 1) / b; }

typedef __nv_bfloat16 bf16;
typedef __half fp16;

// ============================ device scratch ============================
__device__ float g_s1[3 * NN * H1D];
__device__ float g_s2[3 * NN * H2D];
__device__ float g_emb1[NN * H2D];
__device__ float g_emb3[NN * H2D];
__device__ float g_vsum4[4 * NN * H2D];
__device__ float g_vsum[NN * H2D];
__device__ float g_g2[NN * H2D];
__device__ float g_rowsum[NN];
__device__ float g_emb1t[H2D * NN];
__device__ int   g_cnt[NN];
__device__ int   g_cur[NN];
__device__ int   g_rowptr[NN + 1];
__device__ int   g_ccol[NE];
__device__ float g_cval[NE];
// fp16 2-term path: encoder GEMM1
__device__ fp16 g_fA_h[3 * NN * FIN],  g_fA_l[3 * NN * FIN];
__device__ fp16 g_w1t[H1D * FIN];
// bf16 3-term path: GEMM2 + Wd
__device__ bf16 g_h_h [3 * NN * LDH],  g_h_l [3 * NN * LDH];
__device__ bf16 g_z1_h[NN * H2D],  g_z1_l[NN * H2D];
__device__ bf16 g_w2t_h[H2D * LDH], g_w2t_l[H2D * LDH];
__device__ bf16 g_wdt_h[H1D * H2D], g_wdt_l[H1D * H2D];
// fp16 2-term path: decoder + rec_adj
__device__ fp16 g_xd_h[NN * LDH],  g_xd_l[NN * LDH];
__device__ fp16 g_zn_h[NN * H2D],  g_zn_l[NN * H2D];
__device__ fp16 g_wzt[3 * FIN * LDH];

// ============================ CSR build ============================
__global__ void count_kernel(const int* __restrict__ rows, int* __restrict__ cnt, int e) {
    int i = blockIdx.x * blockDim.x + threadIdx.x;
    if (i < e) atomicAdd(&cnt[rows[i]], 1);
}

__global__ void scan_kernel(const int* __restrict__ cnt, int* __restrict__ rowptr, int n) {
    __shared__ int sums[1024];
    const int PER = 10;
    int tid = threadIdx.x;
    int base = tid * PER;
    int local[PER];
    int s = 0;
    #pragma unroll
    for (int i = 0; i < PER; ++i) {
        int idx = base + i;
        int v = (idx < n) ? cnt[idx] : 0;
        local[i] = s;
        s += v;
    }
    sums[tid] = s;
    __syncthreads();
    for (int off = 1; off < 1024; off <<= 1) {
        int v = (tid >= off) ? sums[tid - off] : 0;
        __syncthreads();
        sums[tid] += v;
        __syncthreads();
    }
    int offset = (tid > 0) ? sums[tid - 1] : 0;
    #pragma unroll
    for (int i = 0; i < PER; ++i) {
        int idx = base + i;
        if (idx < n) rowptr[idx] = offset + local[i];
    }
    if (tid == 1023) rowptr[n] = sums[1023];
}

__global__ void scatter_kernel(const int* __restrict__ rows, const int* __restrict__ cols,
                               const float* __restrict__ vals,
                               const int* __restrict__ rowptr, int* __restrict__ cur,
                               int* __restrict__ ccol, float* __restrict__ cval, int e) {
    int i = blockIdx.x * blockDim.x + threadIdx.x;
    if (i < e) {
        int r = rows[i];
        int p = rowptr[r] + atomicAdd(&cur[r], 1);
        ccol[p] = cols[i];
        cval[p] = vals[i];
    }
}

// ============================ splits ============================
__device__ __forceinline__ void splitf(float v, bf16& h, bf16& l) {
    h = __float2bfloat16(v);
    l = __float2bfloat16(v - __bfloat162float(h));
}
__device__ __forceinline__ void splitf16(float v, fp16& h, fp16& l) {
    h = __float2half_rn(v);
    l = __float2half_rn(v - __half2float(h));
}

__global__ void split_f16_kernel(const float* __restrict__ in, fp16* __restrict__ hi,
                                 fp16* __restrict__ lo, int n4) {
    int i = blockIdx.x * blockDim.x + threadIdx.x;
    if (i >= n4) return;
    float4 v = ((const float4*)in)[i];
    fp16 h0, l0, h1, l1, h2, l2, h3, l3;
    splitf16(v.x, h0, l0); splitf16(v.y, h1, l1);
    splitf16(v.z, h2, l2); splitf16(v.w, h3, l3);
    ((ushort4*)hi)[i] = make_ushort4(__half_as_ushort(h0), __half_as_ushort(h1),
                                     __half_as_ushort(h2), __half_as_ushort(h3));
    ((ushort4*)lo)[i] = make_ushort4(__half_as_ushort(l0), __half_as_ushort(l1),
                                     __half_as_ushort(l2), __half_as_ushort(l3));
}

__global__ void split_bf_kernel(const float* __restrict__ in, bf16* __restrict__ hi,
                                bf16* __restrict__ lo, int n4) {
    int i = blockIdx.x * blockDim.x + threadIdx.x;
    if (i >= n4) return;
    float4 v = ((const float4*)in)[i];
    bf16 h0, l0, h1, l1, h2, l2, h3, l3;
    splitf(v.x, h0, l0); splitf(v.y, h1, l1);
    splitf(v.z, h2, l2); splitf(v.w, h3, l3);
    ((ushort4*)hi)[i] = make_ushort4(__bfloat16_as_ushort(h0), __bfloat16_as_ushort(h1),
                                     __bfloat16_as_ushort(h2), __bfloat16_as_ushort(h3));
    ((ushort4*)lo)[i] = make_ushort4(__bfloat16_as_ushort(l0), __bfloat16_as_ushort(l1),
                                     __bfloat16_as_ushort(l2), __bfloat16_as_ushort(l3));
}

__global__ void transpose_split_kernel(const float* __restrict__ in,
                                       bf16* __restrict__ outh, bf16* __restrict__ outl,
                                       int R, int C, int LDO) {
    __shared__ float t[32][33];
    int c0 = blockIdx.x * 32, r0 = blockIdx.y * 32;
    int x = threadIdx.x, y = threadIdx.y;
    #pragma unroll
    for (int j = 0; j < 32; j += 8) {
        int r = r0 + y + j, c = c0 + x;
        if (r < R && c < C) t[y + j][x] = in[(size_t)r * C + c];
    }
    __syncthreads();
    #pragma unroll
    for (int j = 0; j < 32; j += 8) {
        int r = c0 + y + j, c = r0 + x;
        if (r < C && c < R) {
            bf16 h, l;
            splitf(t[x][y + j], h, l);
            outh[(size_t)r * LDO + c] = h;
            outl[(size_t)r * LDO + c] = l;
        }
    }
}

__global__ void transpose_quant_f16(const float* __restrict__ in, fp16* __restrict__ outp,
                                    int R, int C, int LDO) {
    __shared__ float t[32][33];
    int c0 = blockIdx.x * 32, r0 = blockIdx.y * 32;
    int x = threadIdx.x, y = threadIdx.y;
    #pragma unroll
    for (int j = 0; j < 32; j += 8) {
        int r = r0 + y + j, c = c0 + x;
        if (r < R && c < C) t[y + j][x] = in[(size_t)r * C + c];
    }
    __syncthreads();
    #pragma unroll
    for (int j = 0; j < 32; j += 8) {
        int r = c0 + y + j, c = r0 + x;
        if (r < C && c < R) outp[(size_t)r * LDO + c] = __float2half_rn(t[x][y + j]);
    }
}

__global__ void transpose_kernel(const float* __restrict__ in, float* __restrict__ out, int R, int C) {
    __shared__ float t[32][33];
    int c0 = blockIdx.x * 32, r0 = blockIdx.y * 32;
    int x = threadIdx.x, y = threadIdx.y;
    #pragma unroll
    for (int j = 0; j < 32; j += 8) {
        int r = r0 + y + j, c = c0 + x;
        if (r < R && c < C) t[y + j][x] = in[(size_t)r * C + c];
    }
    __syncthreads();
    #pragma unroll
    for (int j = 0; j < 32; j += 8) {
        int r = c0 + y + j, c = r0 + x;
        if (r < C && c < R) out[(size_t)r * R + c] = t[x][y + j];
    }
}

// ============================ sparse aggregation (batched via grid.z) ============================
__global__ void agg_kernel(const float* __restrict__ src, float* __restrict__ dst,
                           const int* __restrict__ rowptr, const int* __restrict__ ccol,
                           const float* __restrict__ cval, int width, int do_relu,
                           long long zsrc, long long zdst) {
    src += (long long)blockIdx.z * zsrc;
    dst += (long long)blockIdx.z * zdst;
    int r = blockIdx.y;
    int col = blockIdx.x * 128 + threadIdx.x;
    if (col >= width) return;
    int s = rowptr[r], e = rowptr[r + 1];
    float acc = 0.f;
    for (int j = s; j < e; ++j) {
        acc += cval[j] * src[(long long)ccol[j] * width + col];
    }
    if (do_relu) acc = fmaxf(acc, 0.f);
    dst[(long long)r * width + col] = acc;
}

__global__ void agg_split_kernel(const float* __restrict__ src,
                                 bf16* __restrict__ dh, bf16* __restrict__ dl,
                                 const int* __restrict__ rowptr, const int* __restrict__ ccol,
                                 const float* __restrict__ cval, int width, int ldo,
                                 long long zsrc, long long zdst) {
    src += (long long)blockIdx.z * zsrc;
    dh  += (long long)blockIdx.z * zdst;
    dl  += (long long)blockIdx.z * zdst;
    int r = blockIdx.y;
    int col = blockIdx.x * 128 + threadIdx.x;
    if (col >= width) return;
    int s = rowptr[r], e = rowptr[r + 1];
    float acc = 0.f;
    for (int j = s; j < e; ++j) {
        acc += cval[j] * src[(long long)ccol[j] * width + col];
    }
    acc = fmaxf(acc, 0.f);
    bf16 h, l;
    splitf(acc, h, l);
    dh[(long long)r * ldo + col] = h;
    dl[(long long)r * ldo + col] = l;
}

// ============================ epilogue ============================
template <int MODE>
__device__ __forceinline__ float epi(float v, int gc,
                                     const float* p1, const float* p2, const float* p3,
                                     const float* p4, const float* p5) {
    if (MODE == 1) {
        v += __ldg(p1 + gc);
        v = __ldg(p2 + gc) * (v - __ldg(p4 + gc)) * rsqrtf(__ldg(p5 + gc) + BN_EPS) + __ldg(p3 + gc);
        v = fmaxf(v, 0.f);
    } else if (MODE == 2) {
        v += __ldg(p1 + gc);
        v = 1.f / (1.f + expf(-v));
    } else if (MODE == 3) {
        v += __ldg(p1 + gc);
        v = fmaxf(v, 0.f) + log1pf(expf(-fabsf(v)));
        v = fminf(fmaxf(v, 1e-4f), 1e4f);
    } else if (MODE == 4) {
        v += __ldg(p1 + gc);
        v = expf(v);
        v = fminf(fmaxf(v, 1e-5f), 1e6f);
    } else if (MODE == 5) {
        v = 1.f / (1.f + expf(-v));
    }
    return v;
}

template <int MODE>
__device__ __forceinline__ float epi_sel(int bz, float v, int gc,
                                         const float* p1, const float* p2, const float* p3,
                                         const float* p4, const float* p5) {
    if (MODE != 6) return epi<MODE>(v, gc, p1, p2, p3, p4, p5);
    if (bz == 0) return epi<2>(v, gc, p1, nullptr, nullptr, nullptr, nullptr);
    if (bz == 1) return epi<3>(v, gc, p2, nullptr, nullptr, nullptr, nullptr);
    return epi<4>(v, gc, p3, nullptr, nullptr, nullptr, nullptr);
}

// ============================ MMA / LDSM helpers ============================
__device__ __forceinline__ void mma_bf16(float* d, const uint32_t* a, const uint32_t* b) {
    asm volatile(
        "mma.sync.aligned.m16n8k16.row.col.f32.bf16.bf16.f32 "
        "{%0,%1,%2,%3}, {%4,%5,%6,%7}, {%8,%9}, {%0,%1,%2,%3};"
        : "+f"(d[0]), "+f"(d[1]), "+f"(d[2]), "+f"(d[3])
        : "r"(a[0]), "r"(a[1]), "r"(a[2]), "r"(a[3]), "r"(b[0]), "r"(b[1]));
}
__device__ __forceinline__ void mma_f16(float* d, const uint32_t* a, const uint32_t* b) {
    asm volatile(
        "mma.sync.aligned.m16n8k16.row.col.f32.f16.f16.f32 "
        "{%0,%1,%2,%3}, {%4,%5,%6,%7}, {%8,%9}, {%0,%1,%2,%3};"
        : "+f"(d[0]), "+f"(d[1]), "+f"(d[2]), "+f"(d[3])
        : "r"(a[0]), "r"(a[1]), "r"(a[2]), "r"(a[3]), "r"(b[0]), "r"(b[1]));
}
__device__ __forceinline__ void ldsm_x4(uint32_t& r0, uint32_t& r1, uint32_t& r2, uint32_t& r3,
                                        uint32_t addr) {
    asm volatile("ldmatrix.sync.aligned.m8n8.x4.shared.b16 {%0,%1,%2,%3}, [%4];"
                 : "=r"(r0), "=r"(r1), "=r"(r2), "=r"(r3) : "r"(addr));
}

__device__ __forceinline__ void bfsplit2(float x, float y, uint32_t& hi, uint32_t& lo) {
    uint32_t h;
    asm("cvt.rn.bf16x2.f32 %0, %1, %2;" : "=r"(h) : "f"(y), "f"(x));
    float xh = __uint_as_float(h << 16);
    float yh = __uint_as_float(h & 0xffff0000u);
    float xl = x - xh;
    float yl = y - yh;
    uint32_t l;
    asm("cvt.rn.bf16x2.f32 %0, %1, %2;" : "=r"(l) : "f"(yl), "f"(xl));
    hi = h; lo = l;
}

__device__ __forceinline__ void cp_async16(uint32_t saddr, const void* gaddr, int src_size) {
    asm volatile("cp.async.cg.shared.global [%0], [%1], 16, %2;"
                 :: "r"(saddr), "l"(gaddr), "r"(src_size) : "memory");
}

__device__ __forceinline__ uint32_t smem_u32(const void* p) {
    uint32_t a;
    asm("{ .reg .u64 t; cvta.to.shared.u64 t, %1; cvt.u32.u64 %0, t; }" : "=r"(a) : "l"(p));
    return a;
}

// ============================ bf16 3-term GEMM (batched, ldmatrix, 2-stage) ============================
#define BROWB 80

template <int NT>
__device__ __forceinline__ void load_stage_bf(const bf16* __restrict__ Ah, const bf16* __restrict__ Al,
                                              const bf16* __restrict__ Bh, const bf16* __restrict__ Bl,
                                              int M, int N, int K, int lda, int ldb,
                                              int rowBase, int colBase, int k0,
                                              uint32_t sb, int tid) {
    #pragma unroll
    for (int i = 0; i < 2; ++i) {
        int idx = tid + i * 256;
        int row = idx >> 2, c = idx & 3;
        int gr = rowBase + row, gk = k0 + c * 8;
        int sz = 0;
        if (gr < M) { int rem = (K - gk) * 2; sz = rem >= 16 ? 16 : (rem > 0 ? rem : 0); }
        uint32_t off = row * BROWB + c * 16;
        cp_async16(sb + off, Ah + (size_t)gr * lda + gk, sz);
        cp_async16(sb + 128 * BROWB + off, Al + (size_t)gr * lda + gk, sz);
    }
    uint32_t bbase = sb + 2 * 128 * BROWB;
    #pragma unroll
    for (int i = 0; i < NT / 64; ++i) {
        int idx = tid + i * 256;
        int row = idx >> 2, c = idx & 3;
        int gn = colBase + row, gk = k0 + c * 8;
        int sz = 0;
        if (gn < N) { int rem = (K - gk) * 2; sz = rem >= 16 ? 16 : (rem > 0 ? rem : 0); }
        uint32_t off = row * BROWB + c * 16;
        cp_async16(bbase + off, Bh + (size_t)gn * ldb + gk, sz);
        cp_async16(bbase + NT * BROWB + off, Bl + (size_t)gn * ldb + gk, sz);
    }
}

template <int NT, int MODE>
__global__ void __launch_bounds__(256, 2)
tb_gemm(const bf16* __restrict__ Ah, const bf16* __restrict__ Al,
        const bf16* __restrict__ Bh, const bf16* __restrict__ Bl,
        float* __restrict__ C, fp16* __restrict__ Ch, fp16* __restrict__ Cl,
        int M, int N, int K, int lda, int ldb, int ldc,
        long long strideA, long long strideB, long long strideC,
        const float* __restrict__ p1, const float* __restrict__ p2,
        const float* __restrict__ p3, const float* __restrict__ p4,
        const float* __restrict__ p5) {
    constexpr int STAGEB = (256 + 2 * NT) * BROWB;
    constexpr int NMI = (NT == 128) ? 4 : 2;
    const int bz = blockIdx.z;
    Ah += (long long)bz * strideA; Al += (long long)bz * strideA;
    Bh += (long long)bz * strideB; Bl += (long long)bz * strideB;
    if (C)  C  += (long long)bz * strideC;
    if (Ch) { Ch += (long long)bz * strideC; Cl += (long long)bz * strideC; }

    extern __shared__ char smc[];
    uint32_t sbase = smem_u32(smc);
    const int tid = threadIdx.x;
    const int wid = tid >> 5, lane = tid & 31;
    const int warpM = (NT == 128) ? (wid & 1) : (wid & 3);
    const int warpN = (NT == 128) ? (wid >> 1) : (wid >> 2);
    const int mtile = (NT == 128) ? 64 : 32;
    const int rowBase = blockIdx.y * 128;
    const int colBase = blockIdx.x * NT;
    const int nt = (K + 31) >> 5;
    const int lr = lane >> 2, lc = lane & 3;
    const int lrow = lane & 7;

    uint32_t a_off[NMI], b_off[2];
    #pragma unroll
    for (int mi = 0; mi < NMI; ++mi)
        a_off[mi] = (uint32_t)((warpM * mtile + mi * 16 + ((lane >> 3) & 1) * 8 + lrow) * BROWB
                               + (lane >> 4) * 16);
    #pragma unroll
    for (int pr = 0; pr < 2; ++pr)
        b_off[pr] = (uint32_t)((warpN * 32 + pr * 16 + (lane >> 4) * 8 + lrow) * BROWB
                               + ((lane >> 3) & 1) * 16);

    float acc[NMI][4][4];
    #pragma unroll
    for (int i = 0; i < NMI; ++i)
        #pragma unroll
        for (int j = 0; j < 4; ++j)
            #pragma unroll
            for (int k = 0; k < 4; ++k) acc[i][j][k] = 0.f;

    load_stage_bf<NT>(Ah, Al, Bh, Bl, M, N, K, lda, ldb, rowBase, colBase, 0, sbase, tid);
    asm volatile("cp.async.commit_group;" ::: "memory");

    for (int t = 0; t < nt; ++t) {
        if (t + 1 < nt) {
            load_stage_bf<NT>(Ah, Al, Bh, Bl, M, N, K, lda, ldb, rowBase, colBase, (t + 1) << 5,
                              sbase + ((t + 1) & 1) * STAGEB, tid);
            asm volatile("cp.async.commit_group;" ::: "memory");
            asm volatile("cp.async.wait_group 1;" ::: "memory");
        } else {
            asm volatile("cp.async.wait_group 0;" ::: "memory");
        }
        __syncthreads();

        uint32_t sA_u = sbase + (t & 1) * STAGEB;
        uint32_t sB_u = sA_u + 2 * 128 * BROWB;

        #pragma unroll
        for (int kb = 0; kb < 2; ++kb) {
            uint32_t kb2 = kb * 32;
            uint32_t ah[NMI][4], al[NMI][4], bh[4][2], bl[4][2];
            #pragma unroll
            for (int mi = 0; mi < NMI; ++mi) {
                ldsm_x4(ah[mi][0], ah[mi][1], ah[mi][2], ah[mi][3], sA_u + a_off[mi] + kb2);
                ldsm_x4(al[mi][0], al[mi][1], al[mi][2], al[mi][3],
                        sA_u + 128 * BROWB + a_off[mi] + kb2);
            }
            #pragma unroll
            for (int pr = 0; pr < 2; ++pr) {
                ldsm_x4(bh[pr * 2][0], bh[pr * 2][1], bh[pr * 2 + 1][0], bh[pr * 2 + 1][1],
                        sB_u + b_off[pr] + kb2);
                ldsm_x4(bl[pr * 2][0], bl[pr * 2][1], bl[pr * 2 + 1][0], bl[pr * 2 + 1][1],
                        sB_u + NT * BROWB + b_off[pr] + kb2);
            }
            #pragma unroll
            for (int mi = 0; mi < NMI; ++mi)
                #pragma unroll
                for (int ni = 0; ni < 4; ++ni) {
                    mma_bf16(acc[mi][ni], ah[mi], bh[ni]);
                    mma_bf16(acc[mi][ni], ah[mi], bl[ni]);
                    mma_bf16(acc[mi][ni], al[mi], bh[ni]);
                }
        }
        __syncthreads();
    }

    #pragma unroll
    for (int mi = 0; mi < NMI; ++mi) {
        int r0 = rowBase + warpM * mtile + mi * 16 + lr;
        #pragma unroll
        for (int ni = 0; ni < 4; ++ni) {
            int gc = colBase + warpN * 32 + ni * 8 + lc * 2;
            if (gc >= N) continue;
            #pragma unroll
            for (int half = 0; half < 2; ++half) {
                int gr = r0 + half * 8;
                if (gr >= M) continue;
                float vx = epi_sel<MODE>(bz, acc[mi][ni][half * 2 + 0], gc,     p1, p2, p3, p4, p5);
                float vy = epi_sel<MODE>(bz, acc[mi][ni][half * 2 + 1], gc + 1, p1, p2, p3, p4, p5);
                if (MODE == 1) {
                    fp16 h, l;
                    size_t idx = (size_t)gr * ldc + gc;
                    splitf16(vx, h, l); Ch[idx] = h; Cl[idx] = l;
                    splitf16(vy, h, l); Ch[idx + 1] = h; Cl[idx + 1] = l;
                } else {
                    *(float2*)&C[(size_t)gr * ldc + gc] = make_float2(vx, vy);
                }
            }
        }
    }
}

template <int NT, int MODE>
static void launch_tb(const bf16* Ah, const bf16* Al, const bf16* Bh, const bf16* Bl,
                      float* C, fp16* Ch, fp16* Cl, int M, int N, int K,
                      int lda, int ldb, int ldc, int nz,
                      long long sA, long long sB, long long sC,
                      const float* p1 = nullptr, const float* p2 = nullptr,
                      const float* p3 = nullptr, const float* p4 = nullptr,
                      const float* p5 = nullptr) {
    constexpr int SMEMSZ = 2 * (256 + 2 * NT) * BROWB;
    cudaFuncSetAttribute(tb_gemm<NT, MODE>, cudaFuncAttributeMaxDynamicSharedMemorySize, SMEMSZ);
    dim3 grid(cdiv(N, NT), cdiv(M, 128), nz);
    tb_gemm<NT, MODE><<<grid, 256, SMEMSZ>>>(Ah, Al, Bh, Bl, C, Ch, Cl, M, N, K,
                                             lda, ldb, ldc, sA, sB, sC, p1, p2, p3, p4, p5);
}

// ============================ fp16 2-term GEMM (ldmatrix, 3-stage) ============================
#define T2STAGES 3

template <int NT>
__device__ __forceinline__ void load_stage_f16(const fp16* __restrict__ Ah, const fp16* __restrict__ Al,
                                               const fp16* __restrict__ Bh,
                                               int M, int N, int K, int lda, int ldb,
                                               int rowBase, int colBase, int k0,
                                               uint32_t sb, int tid) {
    #pragma unroll
    for (int i = 0; i < 2; ++i) {
        int idx = tid + i * 256;
        int row = idx >> 2, c = idx & 3;
        int gr = rowBase + row, gk = k0 + c * 8;
        int sz = 0;
        if (gr < M) { int rem = (K - gk) * 2; sz = rem >= 16 ? 16 : (rem > 0 ? rem : 0); }
        uint32_t off = row * BROWB + c * 16;
        cp_async16(sb + off, Ah + (size_t)gr * lda + gk, sz);
        cp_async16(sb + 128 * BROWB + off, Al + (size_t)gr * lda + gk, sz);
    }
    uint32_t bbase = sb + 2 * 128 * BROWB;
    #pragma unroll
    for (int i = 0; i < NT / 64; ++i) {
        int idx = tid + i * 256;
        int row = idx >> 2, c = idx & 3;
        int gn = colBase + row, gk = k0 + c * 8;
        int sz = 0;
        if (gn < N) { int rem = (K - gk) * 2; sz = rem >= 16 ? 16 : (rem > 0 ? rem : 0); }
        uint32_t off = row * BROWB + c * 16;
        cp_async16(bbase + off, Bh + (size_t)gn * ldb + gk, sz);
    }
}

template <int NT, int MODE>
__global__ void __launch_bounds__(256, 2)
t2_gemm(const fp16* __restrict__ Ah, const fp16* __restrict__ Al,
        const fp16* __restrict__ Bh,
        float* __restrict__ C,
        int M, int N, int K, int lda, int ldb, int ldc,
        long long strideA, long long strideB, long long strideC,
        const float* __restrict__ p1, const float* __restrict__ p2,
        const float* __restrict__ p3, const float* __restrict__ p4,
        const float* __restrict__ p5) {
    constexpr int STAGEB = (256 + NT) * BROWB;
    constexpr int NMI = (NT == 128) ? 4 : 2;
    const int bz = blockIdx.z;
    Ah += (long long)bz * strideA; Al += (long long)bz * strideA;
    Bh += (long long)bz * strideB;
    C  += (long long)bz * strideC;

    extern __shared__ char smc[];
    uint32_t sbase = smem_u32(smc);
    const int tid = threadIdx.x;
    const int wid = tid >> 5, lane = tid & 31;
    const int warpM = (NT == 128) ? (wid & 1) : (wid & 3);
    const int warpN = (NT == 128) ? (wid >> 1) : (wid >> 2);
    const int mtile = (NT == 128) ? 64 : 32;
    const int rowBase = blockIdx.y * 128;
    const int colBase = blockIdx.x * NT;
    const int nt = (K + 31) >> 5;
    const int lr = lane >> 2, lc = lane & 3;
    const int lrow = lane & 7;

    uint32_t a_off[NMI], b_off[2];
    #pragma unroll
    for (int mi = 0; mi < NMI; ++mi)
        a_off[mi] = (uint32_t)((warpM * mtile + mi * 16 + ((lane >> 3) & 1) * 8 + lrow) * BROWB
                               + (lane >> 4) * 16);
    #pragma unroll
    for (int pr = 0; pr < 2; ++pr)
        b_off[pr] = (uint32_t)((warpN * 32 + pr * 16 + (lane >> 4) * 8 + lrow) * BROWB
                               + ((lane >> 3) & 1) * 16);

    float acc[NMI][4][4];
    #pragma unroll
    for (int i = 0; i < NMI; ++i)
        #pragma unroll
        for (int j = 0; j < 4; ++j)
            #pragma unroll
            for (int k = 0; k < 4; ++k) acc[i][j][k] = 0.f;

    // 3-stage prologue
    #pragma unroll
    for (int t = 0; t < 2; ++t) {
        if (t < nt) load_stage_f16<NT>(Ah, Al, Bh, M, N, K, lda, ldb, rowBase, colBase,
                                       t << 5, sbase + t * STAGEB, tid);
        asm volatile("cp.async.commit_group;" ::: "memory");
    }

    for (int t = 0; t < nt; ++t) {
        if (t + 2 < nt)
            load_stage_f16<NT>(Ah, Al, Bh, M, N, K, lda, ldb, rowBase, colBase, (t + 2) << 5,
                               sbase + ((t + 2) % T2STAGES) * STAGEB, tid);
        asm volatile("cp.async.commit_group;" ::: "memory");
        asm volatile("cp.async.wait_group 2;" ::: "memory");
        __syncthreads();

        uint32_t sA_u = sbase + (t % T2STAGES) * STAGEB;
        uint32_t sB_u = sA_u + 2 * 128 * BROWB;

        #pragma unroll
        for (int kb = 0; kb < 2; ++kb) {
            uint32_t kb2 = kb * 32;
            uint32_t ah[NMI][4], al[NMI][4], bh[4][2];
            #pragma unroll
            for (int mi = 0; mi < NMI; ++mi) {
                ldsm_x4(ah[mi][0], ah[mi][1], ah[mi][2], ah[mi][3], sA_u + a_off[mi] + kb2);
                ldsm_x4(al[mi][0], al[mi][1], al[mi][2], al[mi][3],
                        sA_u + 128 * BROWB + a_off[mi] + kb2);
            }
            #pragma unroll
            for (int pr = 0; pr < 2; ++pr) {
                ldsm_x4(bh[pr * 2][0], bh[pr * 2][1], bh[pr * 2 + 1][0], bh[pr * 2 + 1][1],
                        sB_u + b_off[pr] + kb2);
            }
            #pragma unroll
            for (int mi = 0; mi < NMI; ++mi)
                #pragma unroll
                for (int ni = 0; ni < 4; ++ni) {
                    mma_f16(acc[mi][ni], ah[mi], bh[ni]);
                    mma_f16(acc[mi][ni], al[mi], bh[ni]);
                }
        }
        __syncthreads();
    }

    #pragma unroll
    for (int mi = 0; mi < NMI; ++mi) {
        int r0 = rowBase + warpM * mtile + mi * 16 + lr;
        #pragma unroll
        for (int ni = 0; ni < 4; ++ni) {
            int gc = colBase + warpN * 32 + ni * 8 + lc * 2;
            if (gc >= N) continue;
            #pragma unroll
            for (int half = 0; half < 2; ++half) {
                int gr = r0 + half * 8;
                if (gr >= M) continue;
                float vx = epi_sel<MODE>(bz, acc[mi][ni][half * 2 + 0], gc,     p1, p2, p3, p4, p5);
                float vy = epi_sel<MODE>(bz, acc[mi][ni][half * 2 + 1], gc + 1, p1, p2, p3, p4, p5);
                *(float2*)&C[(size_t)gr * ldc + gc] = make_float2(vx, vy);
            }
        }
    }
}

template <int NT, int MODE>
static void launch_t2(const fp16* Ah, const fp16* Al, const fp16* Bh,
                      float* C, int M, int N, int K,
                      int lda, int ldb, int ldc, int nz,
                      long long sA, long long sB, long long sC,
                      const float* p1 = nullptr, const float* p2 = nullptr,
                      const float* p3 = nullptr, const float* p4 = nullptr,
                      const float* p5 = nullptr) {
    constexpr int SMEMSZ = T2STAGES * (256 + NT) * BROWB;
    cudaFuncSetAttribute(t2_gemm<NT, MODE>, cudaFuncAttributeMaxDynamicSharedMemorySize, SMEMSZ);
    dim3 grid(cdiv(N, NT), cdiv(M, 128), nz);
    t2_gemm<NT, MODE><<<grid, 256, SMEMSZ>>>(Ah, Al, Bh, C, M, N, K,
                                             lda, ldb, ldc, sA, sB, sC, p1, p2, p3, p4, p5);
}

// ============================ fp32 split-K GEMM + fused rowsum (readout) ============================
#define STAGES 3
#define ROWB 144
#define NCHUNK 313
#define CPZ 79

__device__ __forceinline__ void load_stage_f64(const float* __restrict__ A, const float* __restrict__ Bt,
                                               int M, int N, int K, int rowBase, int k0,
                                               uint32_t sA, int tid) {
    #pragma unroll
    for (int i = 0; i < 4; ++i) {
        int idx = tid + i * 256;
        int row = idx >> 3, c4 = idx & 7;
        int gr = rowBase + row, gk = k0 + c4 * 4;
        int sz = (gr < M && gk < K) ? 16 : 0;
        cp_async16(sA + row * ROWB + c4 * 16, A + (size_t)gr * K + gk, sz);
    }
    uint32_t sB = sA + 128 * ROWB;
    #pragma unroll
    for (int i = 0; i < 2; ++i) {
        int idx = tid + i * 256;
        int row = idx >> 3, c4 = idx & 7;
        int gn = row, gk = k0 + c4 * 4;
        int sz = (gn < N && gk < K) ? 16 : 0;
        cp_async16(sB + row * ROWB + c4 * 16, Bt + (size_t)gn * K + gk, sz);
    }
}

__global__ void __launch_bounds__(256, 2)
tgemm64sk(const float* __restrict__ A, const float* __restrict__ Bt,
          float* __restrict__ Cpart, float* __restrict__ rowsum,
          int M, int N, int K) {
    constexpr int STAGEB = 192 * ROWB;
    extern __shared__ float sm[];
    uint32_t sbase = smem_u32(sm);
    const int tid = threadIdx.x;
    const int wid = tid >> 5, lane = tid & 31;
    const int warpM = wid & 3, warpN = wid >> 2;
    const int rowBase = blockIdx.y * 128;
    const int zz = blockIdx.z;
    const int c0 = zz * CPZ;
    const int nc = min(CPZ, NCHUNK - c0);
    float* C = Cpart + (size_t)zz * M * N;
    const int lr = lane >> 2, lc = lane & 3;

    float acc[2][4][4];
    #pragma unroll
    for (int i = 0; i < 2; ++i)
        #pragma unroll
        for (int j = 0; j < 4; ++j)
            #pragma unroll
            for (int k = 0; k < 4; ++k) acc[i][j][k] = 0.f;

    #pragma unroll
    for (int t = 0; t < 2; ++t) {
        if (t < nc) load_stage_f64(A, Bt, M, N, K, rowBase, (c0 + t) << 5, sbase + t * STAGEB, tid);
        asm volatile("cp.async.commit_group;" ::: "memory");
    }

    float rsacc = 0.f;
    const int rrow = tid >> 1;
    const int rhalf = tid & 1;

    for (int t = 0; t < nc; ++t) {
        if (t + 2 < nc)
            load_stage_f64(A, Bt, M, N, K, rowBase, (c0 + t + 2) << 5,
                           sbase + ((t + 2) % STAGES) * STAGEB, tid);
        asm volatile("cp.async.commit_group;" ::: "memory");
        asm volatile("cp.async.wait_group 2;" ::: "memory");
        __syncthreads();

        const float* As = sm + (t % STAGES) * (STAGEB / 4);
        const float* Bs = As + 128 * (ROWB / 4);

        {
            const float* pr = As + rrow * 36 + rhalf * 16;
            float s = 0.f;
            #pragma unroll
            for (int j = 0; j < 16; ++j) s += pr[j];
            rsacc += s;
        }

        #pragma unroll
        for (int kb = 0; kb < 32; kb += 16) {
            uint32_t ah[2][4], al[2][4], bh[4][2], bl[4][2];
            #pragma unroll
            for (int mi = 0; mi < 2; ++mi) {
                const float* p = As + (warpM * 32 + mi * 16 + lr) * 36 + kb + 2 * lc;
                float2 v00 = *(const float2*)(p);
                float2 v10 = *(const float2*)(p + 8 * 36);
                float2 v01 = *(const float2*)(p + 8);
                float2 v11 = *(const float2*)(p + 8 * 36 + 8);
                bfsplit2(v00.x, v00.y, ah[mi][0], al[mi][0]);
                bfsplit2(v10.x, v10.y, ah[mi][1], al[mi][1]);
                bfsplit2(v01.x, v01.y, ah[mi][2], al[mi][2]);
                bfsplit2(v11.x, v11.y, ah[mi][3], al[mi][3]);
            }
            #pragma unroll
            for (int ni = 0; ni < 4; ++ni) {
                const float* p = Bs + (warpN * 32 + ni * 8 + lr) * 36 + kb + 2 * lc;
                float2 w0 = *(const float2*)(p);
                float2 w1 = *(const float2*)(p + 8);
                bfsplit2(w0.x, w0.y, bh[ni][0], bl[ni][0]);
                bfsplit2(w1.x, w1.y, bh[ni][1], bl[ni][1]);
            }
            #pragma unroll
            for (int mi = 0; mi < 2; ++mi)
                #pragma unroll
                for (int ni = 0; ni < 4; ++ni) {
                    mma_bf16(acc[mi][ni], ah[mi], bh[ni]);
                    mma_bf16(acc[mi][ni], ah[mi], bl[ni]);
                    mma_bf16(acc[mi][ni], al[mi], bh[ni]);
                }
        }
        __syncthreads();
    }

    rsacc += __shfl_xor_sync(0xffffffffu, rsacc, 1);
    if (rhalf == 0) {
        int gr = rowBase + rrow;
        if (gr < M) atomicAdd(&rowsum[gr], rsacc);
    }

    #pragma unroll
    for (int mi = 0; mi < 2; ++mi) {
        int r0 = rowBase + warpM * 32 + mi * 16 + lr;
        #pragma unroll
        for (int ni = 0; ni < 4; ++ni) {
            int gc = warpN * 32 + ni * 8 + lc * 2;
            if (gc >= N) continue;
            if (r0 < M)
                *(float2*)&C[(size_t)r0 * N + gc] = make_float2(acc[mi][ni][0], acc[mi][ni][1]);
            if (r0 + 8 < M)
                *(float2*)&C[(size_t)(r0 + 8) * N + gc] = make_float2(acc[mi][ni][2], acc[mi][ni][3]);
        }
    }
}

__global__ void reduce4_kernel(const float* __restrict__ part, float* __restrict__ outp, int n) {
    int i = blockIdx.x * blockDim.x + threadIdx.x;
    if (i < n) outp[i] = part[i] + part[i + n] + part[i + 2 * n] + part[i + 3 * n];
}

// ============================ small kernels ============================
__global__ void relu_kernel(const float* __restrict__ in, float* __restrict__ out, int n) {
    int i = blockIdx.x * blockDim.x + threadIdx.x;
    if (i < n) out[i] = fmaxf(in[i], 0.f);
}

__global__ void l2norm_split_f16(const float* __restrict__ in,
                                 fp16* __restrict__ oh, fp16* __restrict__ ol, int n) {
    int warp = (blockIdx.x * blockDim.x + threadIdx.x) >> 5;
    int lane = threadIdx.x & 31;
    if (warp >= n) return;
    float v0 = in[warp * 64 + lane];
    float v1 = in[warp * 64 + 32 + lane];
    float ss = v0 * v0 + v1 * v1;
    #pragma unroll
    for (int o = 16; o > 0; o >>= 1) ss += __shfl_xor_sync(0xffffffffu, ss, o);
    float inv = 1.f / fmaxf(sqrtf(ss), 1e-12f);
    fp16 h, l;
    splitf16(v0 * inv, h, l); oh[warp * 64 + lane] = h; ol[warp * 64 + lane] = l;
    splitf16(v1 * inv, h, l); oh[warp * 64 + 32 + lane] = h; ol[warp * 64 + 32 + lane] = l;
}

__global__ void g2_kernel(const float* __restrict__ vsum, const float* __restrict__ rowsum,
                          float* __restrict__ g2, int n) {
    int warp = (blockIdx.x * blockDim.x + threadIdx.x) >> 5;
    int lane = threadIdx.x & 31;
    if (warp >= n) return;
    float inv_rs = 1.f / rowsum[warp];
    float v0 = vsum[warp * 64 + lane] * inv_rs;
    float v1 = vsum[warp * 64 + 32 + lane] * inv_rs;
    float ss = v0 * v0 + v1 * v1;
    #pragma unroll
    for (int o = 16; o > 0; o >>= 1) ss += __shfl_xor_sync(0xffffffffu, ss, o);
    float inv = 1.f / fmaxf(sqrtf(ss), 1e-12f);
    v0 *= inv; v1 *= inv;
    g2[warp * 64 + lane] = 1.f / (1.f + expf(-v0));
    g2[warp * 64 + 32 + lane] = 1.f / (1.f + expf(-v1));
}

__global__ void disc_kernel(const float* __restrict__ emb1, const float* __restrict__ emb3,
                            const float* __restrict__ g2, const float* __restrict__ W,
                            const float* __restrict__ bptr, float* __restrict__ ret) {
    __shared__ float g2s[64];
    __shared__ float r1[64], r2[64];
    int r = blockIdx.x, t = threadIdx.x;
    g2s[t] = g2[r * 64 + t];
    __syncthreads();
    float u = 0.f;
    #pragma unroll
    for (int e = 0; e < 64; ++e) u += W[t * 64 + e] * g2s[e];
    r1[t] = emb1[r * 64 + t] * u;
    r2[t] = emb3[r * 64 + t] * u;
    __syncthreads();
    for (int s = 32; s > 0; s >>= 1) {
        if (t < s) { r1[t] += r1[t + s]; r2[t] += r2[t + s]; }
        __syncthreads();
    }
    if (t == 0) {
        float b = bptr[0];
        ret[r * 2 + 0] = r1[0] + b;
        ret[r * 2 + 1] = r2[0] + b;
    }
}

// ============================ host orchestration ============================
extern "C" void kernel_launch(void* const* d_in, const int* in_sizes, int n_in,
                              void* d_out, int out_size) {
    const float* feat     = (const float*)d_in[0];
    const float* feat_a   = (const float*)d_in[1];
    const float* feat_b   = (const float*)d_in[2];
    const int*   adj_rows = (const int*)  d_in[3];
    const int*   adj_cols = (const int*)  d_in[4];
    const float* adj_vals = (const float*)d_in[5];
    const float* graph_ng = (const float*)d_in[6];
    const float* W1       = (const float*)d_in[7];
    const float* W2       = (const float*)d_in[8];
    const float* Wd       = (const float*)d_in[9];
    const float* bd       = (const float*)d_in[10];
    const float* bn_gamma = (const float*)d_in[11];
    const float* bn_beta  = (const float*)d_in[12];
    const float* bn_mean  = (const float*)d_in[13];
    const float* bn_var   = (const float*)d_in[14];
    const float* Wpi      = (const float*)d_in[15];
    const float* bpi      = (const float*)d_in[16];
    const float* Wdisp    = (const float*)d_in[17];
    const float* bdisp    = (const float*)d_in[18];
    const float* Wmean    = (const float*)d_in[19];
    const float* bmean    = (const float*)d_in[20];
    const float* disc_W   = (const float*)d_in[21];
    const float* disc_b   = (const float*)d_in[22];

    float* out = (float*)d_out;
    float* o_z1   = out;
    float* o_pi   = out + 1920000;
    float* o_z3   = out + 1280000;
    float* o_rec  = out + 91920000;
    float* o_ret  = out + 191920000;

    float *s1, *s2, *emb1, *emb3, *vsum4, *vsum, *g2, *rowsum, *cval, *emb1t;
    int *cnt, *cur, *rowptr, *ccol;
    fp16 *fAh, *fAl, *w1t, *xdh, *xdl, *znh, *znl, *wzt;
    bf16 *hh, *hl, *z1h, *z1l, *w2th, *w2tl, *wdth, *wdtl;

    cudaGetSymbolAddress((void**)&s1, g_s1);
    cudaGetSymbolAddress((void**)&s2, g_s2);
    cudaGetSymbolAddress((void**)&emb1, g_emb1);
    cudaGetSymbolAddress((void**)&emb3, g_emb3);
    cudaGetSymbolAddress((void**)&vsum4, g_vsum4);
    cudaGetSymbolAddress((void**)&vsum, g_vsum);
    cudaGetSymbolAddress((void**)&g2,   g_g2);
    cudaGetSymbolAddress((void**)&rowsum, g_rowsum);
    cudaGetSymbolAddress((void**)&emb1t,  g_emb1t);
    cudaGetSymbolAddress((void**)&cnt,    g_cnt);
    cudaGetSymbolAddress((void**)&cur,    g_cur);
    cudaGetSymbolAddress((void**)&rowptr, g_rowptr);
    cudaGetSymbolAddress((void**)&ccol,   g_ccol);
    cudaGetSymbolAddress((void**)&cval,   g_cval);
    cudaGetSymbolAddress((void**)&fAh, g_fA_h); cudaGetSymbolAddress((void**)&fAl, g_fA_l);
    cudaGetSymbolAddress((void**)&w1t, g_w1t);
    cudaGetSymbolAddress((void**)&hh,  g_h_h);  cudaGetSymbolAddress((void**)&hl,  g_h_l);
    cudaGetSymbolAddress((void**)&z1h, g_z1_h); cudaGetSymbolAddress((void**)&z1l, g_z1_l);
    cudaGetSymbolAddress((void**)&xdh, g_xd_h); cudaGetSymbolAddress((void**)&xdl, g_xd_l);
    cudaGetSymbolAddress((void**)&znh, g_zn_h); cudaGetSymbolAddress((void**)&znl, g_zn_l);
    cudaGetSymbolAddress((void**)&w2th, g_w2t_h); cudaGetSymbolAddress((void**)&w2tl, g_w2t_l);
    cudaGetSymbolAddress((void**)&wdth, g_wdt_h); cudaGetSymbolAddress((void**)&wdtl, g_wdt_l);
    cudaGetSymbolAddress((void**)&wzt,  g_wzt);

    // ---- CSR build ----
    cudaMemsetAsync(cnt, 0, NN * sizeof(int));
    count_kernel<<<cdiv(NE, 256), 256>>>(adj_rows, cnt, NE);
    scan_kernel<<<1, 1024>>>(cnt, rowptr, NN);
    cudaMemsetAsync(cur, 0, NN * sizeof(int));
    scatter_kernel<<<cdiv(NE, 256), 256>>>(adj_rows, adj_cols, adj_vals,
                                           rowptr, cur, ccol, cval, NE);

    // ---- weight transpose + split / quant ----
    dim3 tb(32, 8);
    transpose_quant_f16<<<dim3(cdiv(H1D, 32), cdiv(FIN, 32)), tb>>>(W1, w1t, FIN, H1D, FIN);
    transpose_split_kernel<<<dim3(cdiv(H2D, 32), cdiv(H1D, 32)), tb>>>(W2, w2th, w2tl, H1D, H2D, LDH);
    transpose_split_kernel<<<dim3(cdiv(H1D, 32), cdiv(H2D, 32)), tb>>>(Wd, wdth, wdtl, H2D, H1D, H2D);
    const long long WZS = (long long)FIN * LDH;
    transpose_quant_f16<<<dim3(cdiv(FIN, 32), cdiv(H1D, 32)), tb>>>(Wpi,   wzt,           H1D, FIN, LDH);
    transpose_quant_f16<<<dim3(cdiv(FIN, 32), cdiv(H1D, 32)), tb>>>(Wdisp, wzt + WZS,     H1D, FIN, LDH);
    transpose_quant_f16<<<dim3(cdiv(FIN, 32), cdiv(H1D, 32)), tb>>>(Wmean, wzt + 2 * WZS, H1D, FIN, LDH);

    // ---- feats split upfront (fp16 2-plane, exact) ----
    const long long FAS = (long long)NN * FIN;
    split_f16_kernel<<<cdiv(NN * FIN / 4, 256), 256>>>(feat,   fAh,           fAl,           NN * FIN / 4);
    split_f16_kernel<<<cdiv(NN * FIN / 4, 256), 256>>>(feat_a, fAh + FAS,     fAl + FAS,     NN * FIN / 4);
    split_f16_kernel<<<cdiv(NN * FIN / 4, 256), 256>>>(feat_b, fAh + 2 * FAS, fAl + 2 * FAS, NN * FIN / 4);

    // ---- batched 3x GCN encode: GEMM1 fp16 2-term (3-stage), GEMM2 bf16 3-term ----
    launch_t2<128, 0>(fAh, fAl, w1t, s1, NN, H1D, FIN,
                      FIN, FIN, H1D, 3, FAS, 0, (long long)NN * H1D);
    agg_split_kernel<<<dim3(cdiv(H1D, 128), NN, 3), 128>>>(s1, hh, hl, rowptr, ccol, cval,
                                                           H1D, LDH, (long long)NN * H1D, (long long)NN * LDH);
    launch_tb<64, 0>(hh, hl, w2th, w2tl, s2, nullptr, nullptr, NN, H2D, H1D,
                     LDH, LDH, H2D, 3, (long long)NN * LDH, 0, (long long)NN * H2D);
    agg_kernel<<<dim3(1, NN, 3), 128>>>(s2, out, rowptr, ccol, cval, H2D, 0,
                                        (long long)NN * H2D, 640000LL);   // writes z1, z2, z3

    relu_kernel<<<cdiv(NN * H2D, 256), 256>>>(o_z1, emb1, NN * H2D);
    relu_kernel<<<cdiv(NN * H2D, 256), 256>>>(o_z3, emb3, NN * H2D);
    split_bf_kernel<<<cdiv(NN * H2D / 4, 256), 256>>>(o_z1, z1h, z1l, NN * H2D / 4);
    l2norm_split_f16<<<cdiv(NN, 8), 256>>>(o_z1, znh, znl, NN);

    // ---- ZINB decoder: hidden (bf16 3-term, writes fp16 planes), then batched fp16 2-term ----
    launch_tb<128, 1>(z1h, z1l, wdth, wdtl, nullptr, xdh, xdl, NN, H1D, H2D,
                      H2D, H2D, LDH, 1, 0, 0, 0, bd, bn_gamma, bn_beta, bn_mean, bn_var);
    launch_t2<128, 6>(xdh, xdl, wzt, o_pi, NN, FIN, H1D,
                      LDH, LDH, FIN, 3, 0, WZS, 30000000LL, bpi, bdisp, bmean);

    // ---- adjacency reconstruction: sigmoid(zn @ zn^T), fp16 2-term ----
    launch_t2<128, 5>(znh, znl, znh, o_rec, NN, NN, H2D,
                      H2D, H2D, NN, 1, 0, 0, 0);

    // ---- readout (split-K GEMM + fused rowsum) + discriminator ----
    cudaMemsetAsync(rowsum, 0, NN * sizeof(float));
    transpose_kernel<<<dim3(cdiv(H2D, 32), cdiv(NN, 32)), tb>>>(emb1, emb1t, NN, H2D);
    {
        constexpr int SMEMSZ = STAGES * 192 * ROWB;
        cudaFuncSetAttribute(tgemm64sk, cudaFuncAttributeMaxDynamicSharedMemorySize, SMEMSZ);
        dim3 grid(1, cdiv(NN, 128), 4);
        tgemm64sk<<<grid, 256, SMEMSZ>>>(graph_ng, emb1t, vsum4, rowsum, NN, H2D, NN);
    }
    reduce4_kernel<<<cdiv(NN * H2D, 256), 256>>>(vsum4, vsum, NN * H2D);
    g2_kernel<<<cdiv(NN, 8), 256>>>(vsum, rowsum, g2, NN);
    disc_kernel<<<NN, 64>>>(emb1, emb3, g2, disc_W, disc_b, o_ret);
}

// round 15
// speedup vs baseline: 1.0192x; 1.0192x over previous
#include <cuda_runtime.h>
#include <cuda_bf16.h>
#include <cuda_fp16.h>
#include <math.h>
#include <stdint.h>

// Problem constants (fixed by the reference)
#define NN   10000
#define FIN  3000
#define H1D  500
#define H2D  64
#define NE   160000
#define BN_EPS 1e-5f
#define LDH  512           // padded leading dim for K=500 operands (16B-aligned rows)

static inline int cdiv(int a, int b) { return (a + b - 1) / b; }

typedef __nv_bfloat16 bf16;
typedef __half fp16;

// ============================ device scratch ============================
__device__ fp16  g_s1[3 * NN * H1D];      // batched GEMM1 out (fp16 storage)
__device__ float g_s2[3 * NN * H2D];
__device__ float g_emb1[NN * H2D];
__device__ float g_emb3[NN * H2D];
__device__ float g_vsum4[4 * NN * H2D];
__device__ float g_vsum[NN * H2D];
__device__ float g_g2[NN * H2D];
__device__ float g_rowsum[NN];
__device__ float g_emb1t[H2D * NN];
__device__ int   g_cnt[NN];
__device__ int   g_cur[NN];
__device__ int   g_rowptr[NN + 1];
__device__ int   g_ccol[NE];
__device__ float g_cval[NE];
// fp16 2-term path: encoder GEMM1
__device__ fp16 g_fA_h[3 * NN * FIN],  g_fA_l[3 * NN * FIN];
__device__ fp16 g_w1t[H1D * FIN];
// bf16 3-term path: GEMM2 + Wd
__device__ bf16 g_h_h [3 * NN * LDH],  g_h_l [3 * NN * LDH];
__device__ bf16 g_z1_h[NN * H2D],  g_z1_l[NN * H2D];
__device__ bf16 g_w2t_h[H2D * LDH], g_w2t_l[H2D * LDH];
__device__ bf16 g_wdt_h[H1D * H2D], g_wdt_l[H1D * H2D];
// fp16 2-term path: decoder + rec_adj
__device__ fp16 g_xd_h[NN * LDH],  g_xd_l[NN * LDH];
__device__ fp16 g_zn_h[NN * H2D],  g_zn_l[NN * H2D];
__device__ fp16 g_wzt[3 * FIN * LDH];

// ============================ CSR build ============================
__global__ void count_kernel(const int* __restrict__ rows, int* __restrict__ cnt, int e) {
    int i = blockIdx.x * blockDim.x + threadIdx.x;
    if (i < e) atomicAdd(&cnt[rows[i]], 1);
}

__global__ void scan_kernel(const int* __restrict__ cnt, int* __restrict__ rowptr, int n) {
    __shared__ int sums[1024];
    const int PER = 10;
    int tid = threadIdx.x;
    int base = tid * PER;
    int local[PER];
    int s = 0;
    #pragma unroll
    for (int i = 0; i < PER; ++i) {
        int idx = base + i;
        int v = (idx < n) ? cnt[idx] : 0;
        local[i] = s;
        s += v;
    }
    sums[tid] = s;
    __syncthreads();
    for (int off = 1; off < 1024; off <<= 1) {
        int v = (tid >= off) ? sums[tid - off] : 0;
        __syncthreads();
        sums[tid] += v;
        __syncthreads();
    }
    int offset = (tid > 0) ? sums[tid - 1] : 0;
    #pragma unroll
    for (int i = 0; i < PER; ++i) {
        int idx = base + i;
        if (idx < n) rowptr[idx] = offset + local[i];
    }
    if (tid == 1023) rowptr[n] = sums[1023];
}

__global__ void scatter_kernel(const int* __restrict__ rows, const int* __restrict__ cols,
                               const float* __restrict__ vals,
                               const int* __restrict__ rowptr, int* __restrict__ cur,
                               int* __restrict__ ccol, float* __restrict__ cval, int e) {
    int i = blockIdx.x * blockDim.x + threadIdx.x;
    if (i < e) {
        int r = rows[i];
        int p = rowptr[r] + atomicAdd(&cur[r], 1);
        ccol[p] = cols[i];
        cval[p] = vals[i];
    }
}

// ============================ splits ============================
__device__ __forceinline__ void splitf(float v, bf16& h, bf16& l) {
    h = __float2bfloat16(v);
    l = __float2bfloat16(v - __bfloat162float(h));
}
__device__ __forceinline__ void splitf16(float v, fp16& h, fp16& l) {
    h = __float2half_rn(v);
    l = __float2half_rn(v - __half2float(h));
}

__global__ void split_f16_kernel(const float* __restrict__ in, fp16* __restrict__ hi,
                                 fp16* __restrict__ lo, int n4) {
    int i = blockIdx.x * blockDim.x + threadIdx.x;
    if (i >= n4) return;
    float4 v = ((const float4*)in)[i];
    fp16 h0, l0, h1, l1, h2, l2, h3, l3;
    splitf16(v.x, h0, l0); splitf16(v.y, h1, l1);
    splitf16(v.z, h2, l2); splitf16(v.w, h3, l3);
    ((ushort4*)hi)[i] = make_ushort4(__half_as_ushort(h0), __half_as_ushort(h1),
                                     __half_as_ushort(h2), __half_as_ushort(h3));
    ((ushort4*)lo)[i] = make_ushort4(__half_as_ushort(l0), __half_as_ushort(l1),
                                     __half_as_ushort(l2), __half_as_ushort(l3));
}

__global__ void split_bf_kernel(const float* __restrict__ in, bf16* __restrict__ hi,
                                bf16* __restrict__ lo, int n4) {
    int i = blockIdx.x * blockDim.x + threadIdx.x;
    if (i >= n4) return;
    float4 v = ((const float4*)in)[i];
    bf16 h0, l0, h1, l1, h2, l2, h3, l3;
    splitf(v.x, h0, l0); splitf(v.y, h1, l1);
    splitf(v.z, h2, l2); splitf(v.w, h3, l3);
    ((ushort4*)hi)[i] = make_ushort4(__bfloat16_as_ushort(h0), __bfloat16_as_ushort(h1),
                                     __bfloat16_as_ushort(h2), __bfloat16_as_ushort(h3));
    ((ushort4*)lo)[i] = make_ushort4(__bfloat16_as_ushort(l0), __bfloat16_as_ushort(l1),
                                     __bfloat16_as_ushort(l2), __bfloat16_as_ushort(l3));
}

__global__ void transpose_split_kernel(const float* __restrict__ in,
                                       bf16* __restrict__ outh, bf16* __restrict__ outl,
                                       int R, int C, int LDO) {
    __shared__ float t[32][33];
    int c0 = blockIdx.x * 32, r0 = blockIdx.y * 32;
    int x = threadIdx.x, y = threadIdx.y;
    #pragma unroll
    for (int j = 0; j < 32; j += 8) {
        int r = r0 + y + j, c = c0 + x;
        if (r < R && c < C) t[y + j][x] = in[(size_t)r * C + c];
    }
    __syncthreads();
    #pragma unroll
    for (int j = 0; j < 32; j += 8) {
        int r = c0 + y + j, c = r0 + x;
        if (r < C && c < R) {
            bf16 h, l;
            splitf(t[x][y + j], h, l);
            outh[(size_t)r * LDO + c] = h;
            outl[(size_t)r * LDO + c] = l;
        }
    }
}

__global__ void transpose_quant_f16(const float* __restrict__ in, fp16* __restrict__ outp,
                                    int R, int C, int LDO) {
    __shared__ float t[32][33];
    int c0 = blockIdx.x * 32, r0 = blockIdx.y * 32;
    int x = threadIdx.x, y = threadIdx.y;
    #pragma unroll
    for (int j = 0; j < 32; j += 8) {
        int r = r0 + y + j, c = c0 + x;
        if (r < R && c < C) t[y + j][x] = in[(size_t)r * C + c];
    }
    __syncthreads();
    #pragma unroll
    for (int j = 0; j < 32; j += 8) {
        int r = c0 + y + j, c = r0 + x;
        if (r < C && c < R) outp[(size_t)r * LDO + c] = __float2half_rn(t[x][y + j]);
    }
}

__global__ void transpose_kernel(const float* __restrict__ in, float* __restrict__ out, int R, int C) {
    __shared__ float t[32][33];
    int c0 = blockIdx.x * 32, r0 = blockIdx.y * 32;
    int x = threadIdx.x, y = threadIdx.y;
    #pragma unroll
    for (int j = 0; j < 32; j += 8) {
        int r = r0 + y + j, c = c0 + x;
        if (r < R && c < C) t[y + j][x] = in[(size_t)r * C + c];
    }
    __syncthreads();
    #pragma unroll
    for (int j = 0; j < 32; j += 8) {
        int r = c0 + y + j, c = r0 + x;
        if (r < C && c < R) out[(size_t)r * R + c] = t[x][y + j];
    }
}

// ============================ sparse aggregation (batched via grid.z) ============================
__global__ void agg_kernel(const float* __restrict__ src, float* __restrict__ dst,
                           const int* __restrict__ rowptr, const int* __restrict__ ccol,
                           const float* __restrict__ cval, int width, int do_relu,
                           long long zsrc, long long zdst) {
    src += (long long)blockIdx.z * zsrc;
    dst += (long long)blockIdx.z * zdst;
    int r = blockIdx.y;
    int col = blockIdx.x * 128 + threadIdx.x;
    if (col >= width) return;
    int s = rowptr[r], e = rowptr[r + 1];
    float acc = 0.f;
    for (int j = s; j < e; ++j) {
        acc += cval[j] * src[(long long)ccol[j] * width + col];
    }
    if (do_relu) acc = fmaxf(acc, 0.f);
    dst[(long long)r * width + col] = acc;
}

// agg + relu -> bf16 hi/lo planes; src is fp16
__global__ void agg_split_kernel(const fp16* __restrict__ src,
                                 bf16* __restrict__ dh, bf16* __restrict__ dl,
                                 const int* __restrict__ rowptr, const int* __restrict__ ccol,
                                 const float* __restrict__ cval, int width, int ldo,
                                 long long zsrc, long long zdst) {
    src += (long long)blockIdx.z * zsrc;
    dh  += (long long)blockIdx.z * zdst;
    dl  += (long long)blockIdx.z * zdst;
    int r = blockIdx.y;
    int col = blockIdx.x * 128 + threadIdx.x;
    if (col >= width) return;
    int s = rowptr[r], e = rowptr[r + 1];
    float acc = 0.f;
    for (int j = s; j < e; ++j) {
        acc += cval[j] * __half2float(src[(long long)ccol[j] * width + col]);
    }
    acc = fmaxf(acc, 0.f);
    bf16 h, l;
    splitf(acc, h, l);
    dh[(long long)r * ldo + col] = h;
    dl[(long long)r * ldo + col] = l;
}

// ============================ epilogue ============================
template <int MODE>
__device__ __forceinline__ float epi(float v, int gc,
                                     const float* p1, const float* p2, const float* p3,
                                     const float* p4, const float* p5) {
    if (MODE == 1) {
        v += __ldg(p1 + gc);
        v = __ldg(p2 + gc) * (v - __ldg(p4 + gc)) * rsqrtf(__ldg(p5 + gc) + BN_EPS) + __ldg(p3 + gc);
        v = fmaxf(v, 0.f);
    } else if (MODE == 2) {
        v += __ldg(p1 + gc);
        v = 1.f / (1.f + expf(-v));
    } else if (MODE == 3) {
        v += __ldg(p1 + gc);
        v = fmaxf(v, 0.f) + log1pf(expf(-fabsf(v)));
        v = fminf(fmaxf(v, 1e-4f), 1e4f);
    } else if (MODE == 4) {
        v += __ldg(p1 + gc);
        v = expf(v);
        v = fminf(fmaxf(v, 1e-5f), 1e6f);
    } else if (MODE == 5) {
        v = 1.f / (1.f + expf(-v));
    }
    return v;   // MODE 0 / 7: identity
}

template <int MODE>
__device__ __forceinline__ float epi_sel(int bz, float v, int gc,
                                         const float* p1, const float* p2, const float* p3,
                                         const float* p4, const float* p5) {
    if (MODE != 6) return epi<MODE>(v, gc, p1, p2, p3, p4, p5);
    if (bz == 0) return epi<2>(v, gc, p1, nullptr, nullptr, nullptr, nullptr);
    if (bz == 1) return epi<3>(v, gc, p2, nullptr, nullptr, nullptr, nullptr);
    return epi<4>(v, gc, p3, nullptr, nullptr, nullptr, nullptr);
}

// ============================ MMA / LDSM helpers ============================
__device__ __forceinline__ void mma_bf16(float* d, const uint32_t* a, const uint32_t* b) {
    asm volatile(
        "mma.sync.aligned.m16n8k16.row.col.f32.bf16.bf16.f32 "
        "{%0,%1,%2,%3}, {%4,%5,%6,%7}, {%8,%9}, {%0,%1,%2,%3};"
        : "+f"(d[0]), "+f"(d[1]), "+f"(d[2]), "+f"(d[3])
        : "r"(a[0]), "r"(a[1]), "r"(a[2]), "r"(a[3]), "r"(b[0]), "r"(b[1]));
}
__device__ __forceinline__ void mma_f16(float* d, const uint32_t* a, const uint32_t* b) {
    asm volatile(
        "mma.sync.aligned.m16n8k16.row.col.f32.f16.f16.f32 "
        "{%0,%1,%2,%3}, {%4,%5,%6,%7}, {%8,%9}, {%0,%1,%2,%3};"
        : "+f"(d[0]), "+f"(d[1]), "+f"(d[2]), "+f"(d[3])
        : "r"(a[0]), "r"(a[1]), "r"(a[2]), "r"(a[3]), "r"(b[0]), "r"(b[1]));
}
__device__ __forceinline__ void ldsm_x4(uint32_t& r0, uint32_t& r1, uint32_t& r2, uint32_t& r3,
                                        uint32_t addr) {
    asm volatile("ldmatrix.sync.aligned.m8n8.x4.shared.b16 {%0,%1,%2,%3}, [%4];"
                 : "=r"(r0), "=r"(r1), "=r"(r2), "=r"(r3) : "r"(addr));
}

__device__ __forceinline__ void bfsplit2(float x, float y, uint32_t& hi, uint32_t& lo) {
    uint32_t h;
    asm("cvt.rn.bf16x2.f32 %0, %1, %2;" : "=r"(h) : "f"(y), "f"(x));
    float xh = __uint_as_float(h << 16);
    float yh = __uint_as_float(h & 0xffff0000u);
    float xl = x - xh;
    float yl = y - yh;
    uint32_t l;
    asm("cvt.rn.bf16x2.f32 %0, %1, %2;" : "=r"(l) : "f"(yl), "f"(xl));
    hi = h; lo = l;
}

__device__ __forceinline__ void cp_async16(uint32_t saddr, const void* gaddr, int src_size) {
    asm volatile("cp.async.cg.shared.global [%0], [%1], 16, %2;"
                 :: "r"(saddr), "l"(gaddr), "r"(src_size) : "memory");
}

__device__ __forceinline__ uint32_t smem_u32(const void* p) {
    uint32_t a;
    asm("{ .reg .u64 t; cvta.to.shared.u64 t, %1; cvt.u32.u64 %0, t; }" : "=r"(a) : "l"(p));
    return a;
}

// ============================ bf16 3-term GEMM (batched, ldmatrix, 2-stage) ============================
#define BROWB 80

template <int NT>
__device__ __forceinline__ void load_stage_bf(const bf16* __restrict__ Ah, const bf16* __restrict__ Al,
                                              const bf16* __restrict__ Bh, const bf16* __restrict__ Bl,
                                              int M, int N, int K, int lda, int ldb,
                                              int rowBase, int colBase, int k0,
                                              uint32_t sb, int tid) {
    #pragma unroll
    for (int i = 0; i < 2; ++i) {
        int idx = tid + i * 256;
        int row = idx >> 2, c = idx & 3;
        int gr = rowBase + row, gk = k0 + c * 8;
        int sz = 0;
        if (gr < M) { int rem = (K - gk) * 2; sz = rem >= 16 ? 16 : (rem > 0 ? rem : 0); }
        uint32_t off = row * BROWB + c * 16;
        cp_async16(sb + off, Ah + (size_t)gr * lda + gk, sz);
        cp_async16(sb + 128 * BROWB + off, Al + (size_t)gr * lda + gk, sz);
    }
    uint32_t bbase = sb + 2 * 128 * BROWB;
    #pragma unroll
    for (int i = 0; i < NT / 64; ++i) {
        int idx = tid + i * 256;
        int row = idx >> 2, c = idx & 3;
        int gn = colBase + row, gk = k0 + c * 8;
        int sz = 0;
        if (gn < N) { int rem = (K - gk) * 2; sz = rem >= 16 ? 16 : (rem > 0 ? rem : 0); }
        uint32_t off = row * BROWB + c * 16;
        cp_async16(bbase + off, Bh + (size_t)gn * ldb + gk, sz);
        cp_async16(bbase + NT * BROWB + off, Bl + (size_t)gn * ldb + gk, sz);
    }
}

template <int NT, int MODE>
__global__ void __launch_bounds__(256, 2)
tb_gemm(const bf16* __restrict__ Ah, const bf16* __restrict__ Al,
        const bf16* __restrict__ Bh, const bf16* __restrict__ Bl,
        float* __restrict__ C, fp16* __restrict__ Ch, fp16* __restrict__ Cl,
        int M, int N, int K, int lda, int ldb, int ldc,
        long long strideA, long long strideB, long long strideC,
        const float* __restrict__ p1, const float* __restrict__ p2,
        const float* __restrict__ p3, const float* __restrict__ p4,
        const float* __restrict__ p5) {
    constexpr int STAGEB = (256 + 2 * NT) * BROWB;
    constexpr int NMI = (NT == 128) ? 4 : 2;
    const int bz = blockIdx.z;
    Ah += (long long)bz * strideA; Al += (long long)bz * strideA;
    Bh += (long long)bz * strideB; Bl += (long long)bz * strideB;
    if (C)  C  += (long long)bz * strideC;
    if (Ch) { Ch += (long long)bz * strideC; Cl += (long long)bz * strideC; }

    extern __shared__ char smc[];
    uint32_t sbase = smem_u32(smc);
    const int tid = threadIdx.x;
    const int wid = tid >> 5, lane = tid & 31;
    const int warpM = (NT == 128) ? (wid & 1) : (wid & 3);
    const int warpN = (NT == 128) ? (wid >> 1) : (wid >> 2);
    const int mtile = (NT == 128) ? 64 : 32;
    const int rowBase = blockIdx.y * 128;
    const int colBase = blockIdx.x * NT;
    const int nt = (K + 31) >> 5;
    const int lr = lane >> 2, lc = lane & 3;
    const int lrow = lane & 7;

    uint32_t a_off[NMI], b_off[2];
    #pragma unroll
    for (int mi = 0; mi < NMI; ++mi)
        a_off[mi] = (uint32_t)((warpM * mtile + mi * 16 + ((lane >> 3) & 1) * 8 + lrow) * BROWB
                               + (lane >> 4) * 16);
    #pragma unroll
    for (int pr = 0; pr < 2; ++pr)
        b_off[pr] = (uint32_t)((warpN * 32 + pr * 16 + (lane >> 4) * 8 + lrow) * BROWB
                               + ((lane >> 3) & 1) * 16);

    float acc[NMI][4][4];
    #pragma unroll
    for (int i = 0; i < NMI; ++i)
        #pragma unroll
        for (int j = 0; j < 4; ++j)
            #pragma unroll
            for (int k = 0; k < 4; ++k) acc[i][j][k] = 0.f;

    load_stage_bf<NT>(Ah, Al, Bh, Bl, M, N, K, lda, ldb, rowBase, colBase, 0, sbase, tid);
    asm volatile("cp.async.commit_group;" ::: "memory");

    for (int t = 0; t < nt; ++t) {
        if (t + 1 < nt) {
            load_stage_bf<NT>(Ah, Al, Bh, Bl, M, N, K, lda, ldb, rowBase, colBase, (t + 1) << 5,
                              sbase + ((t + 1) & 1) * STAGEB, tid);
            asm volatile("cp.async.commit_group;" ::: "memory");
            asm volatile("cp.async.wait_group 1;" ::: "memory");
        } else {
            asm volatile("cp.async.wait_group 0;" ::: "memory");
        }
        __syncthreads();

        uint32_t sA_u = sbase + (t & 1) * STAGEB;
        uint32_t sB_u = sA_u + 2 * 128 * BROWB;

        #pragma unroll
        for (int kb = 0; kb < 2; ++kb) {
            uint32_t kb2 = kb * 32;
            uint32_t ah[NMI][4], al[NMI][4], bh[4][2], bl[4][2];
            #pragma unroll
            for (int mi = 0; mi < NMI; ++mi) {
                ldsm_x4(ah[mi][0], ah[mi][1], ah[mi][2], ah[mi][3], sA_u + a_off[mi] + kb2);
                ldsm_x4(al[mi][0], al[mi][1], al[mi][2], al[mi][3],
                        sA_u + 128 * BROWB + a_off[mi] + kb2);
            }
            #pragma unroll
            for (int pr = 0; pr < 2; ++pr) {
                ldsm_x4(bh[pr * 2][0], bh[pr * 2][1], bh[pr * 2 + 1][0], bh[pr * 2 + 1][1],
                        sB_u + b_off[pr] + kb2);
                ldsm_x4(bl[pr * 2][0], bl[pr * 2][1], bl[pr * 2 + 1][0], bl[pr * 2 + 1][1],
                        sB_u + NT * BROWB + b_off[pr] + kb2);
            }
            #pragma unroll
            for (int mi = 0; mi < NMI; ++mi)
                #pragma unroll
                for (int ni = 0; ni < 4; ++ni) {
                    mma_bf16(acc[mi][ni], ah[mi], bh[ni]);
                    mma_bf16(acc[mi][ni], ah[mi], bl[ni]);
                    mma_bf16(acc[mi][ni], al[mi], bh[ni]);
                }
        }
        __syncthreads();
    }

    #pragma unroll
    for (int mi = 0; mi < NMI; ++mi) {
        int r0 = rowBase + warpM * mtile + mi * 16 + lr;
        #pragma unroll
        for (int ni = 0; ni < 4; ++ni) {
            int gc = colBase + warpN * 32 + ni * 8 + lc * 2;
            if (gc >= N) continue;
            #pragma unroll
            for (int half = 0; half < 2; ++half) {
                int gr = r0 + half * 8;
                if (gr >= M) continue;
                float vx = epi_sel<MODE>(bz, acc[mi][ni][half * 2 + 0], gc,     p1, p2, p3, p4, p5);
                float vy = epi_sel<MODE>(bz, acc[mi][ni][half * 2 + 1], gc + 1, p1, p2, p3, p4, p5);
                if (MODE == 1) {
                    fp16 h, l;
                    size_t idx = (size_t)gr * ldc + gc;
                    splitf16(vx, h, l); Ch[idx] = h; Cl[idx] = l;
                    splitf16(vy, h, l); Ch[idx + 1] = h; Cl[idx + 1] = l;
                } else {
                    *(float2*)&C[(size_t)gr * ldc + gc] = make_float2(vx, vy);
                }
            }
        }
    }
}

template <int NT, int MODE>
static void launch_tb(const bf16* Ah, const bf16* Al, const bf16* Bh, const bf16* Bl,
                      float* C, fp16* Ch, fp16* Cl, int M, int N, int K,
                      int lda, int ldb, int ldc, int nz,
                      long long sA, long long sB, long long sC,
                      const float* p1 = nullptr, const float* p2 = nullptr,
                      const float* p3 = nullptr, const float* p4 = nullptr,
                      const float* p5 = nullptr) {
    constexpr int SMEMSZ = 2 * (256 + 2 * NT) * BROWB;
    cudaFuncSetAttribute(tb_gemm<NT, MODE>, cudaFuncAttributeMaxDynamicSharedMemorySize, SMEMSZ);
    dim3 grid(cdiv(N, NT), cdiv(M, 128), nz);
    tb_gemm<NT, MODE><<<grid, 256, SMEMSZ>>>(Ah, Al, Bh, Bl, C, Ch, Cl, M, N, K,
                                             lda, ldb, ldc, sA, sB, sC, p1, p2, p3, p4, p5);
}

// ============================ fp16 2-term GEMM (ldmatrix, 2-stage) ============================
// MODE 7: write raw result as fp16 to C16 (single plane). Other modes: float C.
template <int NT>
__device__ __forceinline__ void load_stage_f16(const fp16* __restrict__ Ah, const fp16* __restrict__ Al,
                                               const fp16* __restrict__ Bh,
                                               int M, int N, int K, int lda, int ldb,
                                               int rowBase, int colBase, int k0,
                                               uint32_t sb, int tid) {
    #pragma unroll
    for (int i = 0; i < 2; ++i) {
        int idx = tid + i * 256;
        int row = idx >> 2, c = idx & 3;
        int gr = rowBase + row, gk = k0 + c * 8;
        int sz = 0;
        if (gr < M) { int rem = (K - gk) * 2; sz = rem >= 16 ? 16 : (rem > 0 ? rem : 0); }
        uint32_t off = row * BROWB + c * 16;
        cp_async16(sb + off, Ah + (size_t)gr * lda + gk, sz);
        cp_async16(sb + 128 * BROWB + off, Al + (size_t)gr * lda + gk, sz);
    }
    uint32_t bbase = sb + 2 * 128 * BROWB;
    #pragma unroll
    for (int i = 0; i < NT / 64; ++i) {
        int idx = tid + i * 256;
        int row = idx >> 2, c = idx & 3;
        int gn = colBase + row, gk = k0 + c * 8;
        int sz = 0;
        if (gn < N) { int rem = (K - gk) * 2; sz = rem >= 16 ? 16 : (rem > 0 ? rem : 0); }
        uint32_t off = row * BROWB + c * 16;
        cp_async16(bbase + off, Bh + (size_t)gn * ldb + gk, sz);
    }
}

template <int NT, int MODE>
__global__ void __launch_bounds__(256, 2)
t2_gemm(const fp16* __restrict__ Ah, const fp16* __restrict__ Al,
        const fp16* __restrict__ Bh,
        float* __restrict__ C, fp16* __restrict__ C16,
        int M, int N, int K, int lda, int ldb, int ldc,
        long long strideA, long long strideB, long long strideC,
        const float* __restrict__ p1, const float* __restrict__ p2,
        const float* __restrict__ p3, const float* __restrict__ p4,
        const float* __restrict__ p5) {
    constexpr int STAGEB = (256 + NT) * BROWB;
    constexpr int NMI = (NT == 128) ? 4 : 2;
    const int bz = blockIdx.z;
    Ah += (long long)bz * strideA; Al += (long long)bz * strideA;
    Bh += (long long)bz * strideB;
    if (C)   C   += (long long)bz * strideC;
    if (C16) C16 += (long long)bz * strideC;

    extern __shared__ char smc[];
    uint32_t sbase = smem_u32(smc);
    const int tid = threadIdx.x;
    const int wid = tid >> 5, lane = tid & 31;
    const int warpM = (NT == 128) ? (wid & 1) : (wid & 3);
    const int warpN = (NT == 128) ? (wid >> 1) : (wid >> 2);
    const int mtile = (NT == 128) ? 64 : 32;
    const int rowBase = blockIdx.y * 128;
    const int colBase = blockIdx.x * NT;
    const int nt = (K + 31) >> 5;
    const int lr = lane >> 2, lc = lane & 3;
    const int lrow = lane & 7;

    uint32_t a_off[NMI], b_off[2];
    #pragma unroll
    for (int mi = 0; mi < NMI; ++mi)
        a_off[mi] = (uint32_t)((warpM * mtile + mi * 16 + ((lane >> 3) & 1) * 8 + lrow) * BROWB
                               + (lane >> 4) * 16);
    #pragma unroll
    for (int pr = 0; pr < 2; ++pr)
        b_off[pr] = (uint32_t)((warpN * 32 + pr * 16 + (lane >> 4) * 8 + lrow) * BROWB
                               + ((lane >> 3) & 1) * 16);

    float acc[NMI][4][4];
    #pragma unroll
    for (int i = 0; i < NMI; ++i)
        #pragma unroll
        for (int j = 0; j < 4; ++j)
            #pragma unroll
            for (int k = 0; k < 4; ++k) acc[i][j][k] = 0.f;

    load_stage_f16<NT>(Ah, Al, Bh, M, N, K, lda, ldb, rowBase, colBase, 0, sbase, tid);
    asm volatile("cp.async.commit_group;" ::: "memory");

    for (int t = 0; t < nt; ++t) {
        if (t + 1 < nt) {
            load_stage_f16<NT>(Ah, Al, Bh, M, N, K, lda, ldb, rowBase, colBase, (t + 1) << 5,
                               sbase + ((t + 1) & 1) * STAGEB, tid);
            asm volatile("cp.async.commit_group;" ::: "memory");
            asm volatile("cp.async.wait_group 1;" ::: "memory");
        } else {
            asm volatile("cp.async.wait_group 0;" ::: "memory");
        }
        __syncthreads();

        uint32_t sA_u = sbase + (t & 1) * STAGEB;
        uint32_t sB_u = sA_u + 2 * 128 * BROWB;

        #pragma unroll
        for (int kb = 0; kb < 2; ++kb) {
            uint32_t kb2 = kb * 32;
            uint32_t ah[NMI][4], al[NMI][4], bh[4][2];
            #pragma unroll
            for (int mi = 0; mi < NMI; ++mi) {
                ldsm_x4(ah[mi][0], ah[mi][1], ah[mi][2], ah[mi][3], sA_u + a_off[mi] + kb2);
                ldsm_x4(al[mi][0], al[mi][1], al[mi][2], al[mi][3],
                        sA_u + 128 * BROWB + a_off[mi] + kb2);
            }
            #pragma unroll
            for (int pr = 0; pr < 2; ++pr) {
                ldsm_x4(bh[pr * 2][0], bh[pr * 2][1], bh[pr * 2 + 1][0], bh[pr * 2 + 1][1],
                        sB_u + b_off[pr] + kb2);
            }
            #pragma unroll
            for (int mi = 0; mi < NMI; ++mi)
                #pragma unroll
                for (int ni = 0; ni < 4; ++ni) {
                    mma_f16(acc[mi][ni], ah[mi], bh[ni]);
                    mma_f16(acc[mi][ni], al[mi], bh[ni]);
                }
        }
        __syncthreads();
    }

    #pragma unroll
    for (int mi = 0; mi < NMI; ++mi) {
        int r0 = rowBase + warpM * mtile + mi * 16 + lr;
        #pragma unroll
        for (int ni = 0; ni < 4; ++ni) {
            int gc = colBase + warpN * 32 + ni * 8 + lc * 2;
            if (gc >= N) continue;
            #pragma unroll
            for (int half = 0; half < 2; ++half) {
                int gr = r0 + half * 8;
                if (gr >= M) continue;
                float vx = epi_sel<MODE>(bz, acc[mi][ni][half * 2 + 0], gc,     p1, p2, p3, p4, p5);
                float vy = epi_sel<MODE>(bz, acc[mi][ni][half * 2 + 1], gc + 1, p1, p2, p3, p4, p5);
                if (MODE == 7) {
                    __half2 hv = __floats2half2_rn(vx, vy);
                    *(__half2*)&C16[(size_t)gr * ldc + gc] = hv;
                } else {
                    *(float2*)&C[(size_t)gr * ldc + gc] = make_float2(vx, vy);
                }
            }
        }
    }
}

template <int NT, int MODE>
static void launch_t2(const fp16* Ah, const fp16* Al, const fp16* Bh,
                      float* C, fp16* C16, int M, int N, int K,
                      int lda, int ldb, int ldc, int nz,
                      long long sA, long long sB, long long sC,
                      const float* p1 = nullptr, const float* p2 = nullptr,
                      const float* p3 = nullptr, const float* p4 = nullptr,
                      const float* p5 = nullptr) {
    constexpr int SMEMSZ = 2 * (256 + NT) * BROWB;
    cudaFuncSetAttribute(t2_gemm<NT, MODE>, cudaFuncAttributeMaxDynamicSharedMemorySize, SMEMSZ);
    dim3 grid(cdiv(N, NT), cdiv(M, 128), nz);
    t2_gemm<NT, MODE><<<grid, 256, SMEMSZ>>>(Ah, Al, Bh, C, C16, M, N, K,
                                             lda, ldb, ldc, sA, sB, sC, p1, p2, p3, p4, p5);
}

// ============================ fp32 split-K GEMM + fused rowsum (readout) ============================
#define STAGES 3
#define ROWB 144
#define NCHUNK 313
#define CPZ 79

__device__ __forceinline__ void load_stage_f64(const float* __restrict__ A, const float* __restrict__ Bt,
                                               int M, int N, int K, int rowBase, int k0,
                                               uint32_t sA, int tid) {
    #pragma unroll
    for (int i = 0; i < 4; ++i) {
        int idx = tid + i * 256;
        int row = idx >> 3, c4 = idx & 7;
        int gr = rowBase + row, gk = k0 + c4 * 4;
        int sz = (gr < M && gk < K) ? 16 : 0;
        cp_async16(sA + row * ROWB + c4 * 16, A + (size_t)gr * K + gk, sz);
    }
    uint32_t sB = sA + 128 * ROWB;
    #pragma unroll
    for (int i = 0; i < 2; ++i) {
        int idx = tid + i * 256;
        int row = idx >> 3, c4 = idx & 7;
        int gn = row, gk = k0 + c4 * 4;
        int sz = (gn < N && gk < K) ? 16 : 0;
        cp_async16(sB + row * ROWB + c4 * 16, Bt + (size_t)gn * K + gk, sz);
    }
}

__global__ void __launch_bounds__(256, 2)
tgemm64sk(const float* __restrict__ A, const float* __restrict__ Bt,
          float* __restrict__ Cpart, float* __restrict__ rowsum,
          int M, int N, int K) {
    constexpr int STAGEB = 192 * ROWB;
    extern __shared__ float sm[];
    uint32_t sbase = smem_u32(sm);
    const int tid = threadIdx.x;
    const int wid = tid >> 5, lane = tid & 31;
    const int warpM = wid & 3, warpN = wid >> 2;
    const int rowBase = blockIdx.y * 128;
    const int zz = blockIdx.z;
    const int c0 = zz * CPZ;
    const int nc = min(CPZ, NCHUNK - c0);
    float* C = Cpart + (size_t)zz * M * N;
    const int lr = lane >> 2, lc = lane & 3;

    float acc[2][4][4];
    #pragma unroll
    for (int i = 0; i < 2; ++i)
        #pragma unroll
        for (int j = 0; j < 4; ++j)
            #pragma unroll
            for (int k = 0; k < 4; ++k) acc[i][j][k] = 0.f;

    #pragma unroll
    for (int t = 0; t < 2; ++t) {
        if (t < nc) load_stage_f64(A, Bt, M, N, K, rowBase, (c0 + t) << 5, sbase + t * STAGEB, tid);
        asm volatile("cp.async.commit_group;" ::: "memory");
    }

    float rsacc = 0.f;
    const int rrow = tid >> 1;
    const int rhalf = tid & 1;

    for (int t = 0; t < nc; ++t) {
        if (t + 2 < nc)
            load_stage_f64(A, Bt, M, N, K, rowBase, (c0 + t + 2) << 5,
                           sbase + ((t + 2) % STAGES) * STAGEB, tid);
        asm volatile("cp.async.commit_group;" ::: "memory");
        asm volatile("cp.async.wait_group 2;" ::: "memory");
        __syncthreads();

        const float* As = sm + (t % STAGES) * (STAGEB / 4);
        const float* Bs = As + 128 * (ROWB / 4);

        {
            const float* pr = As + rrow * 36 + rhalf * 16;
            float s = 0.f;
            #pragma unroll
            for (int j = 0; j < 16; ++j) s += pr[j];
            rsacc += s;
        }

        #pragma unroll
        for (int kb = 0; kb < 32; kb += 16) {
            uint32_t ah[2][4], al[2][4], bh[4][2], bl[4][2];
            #pragma unroll
            for (int mi = 0; mi < 2; ++mi) {
                const float* p = As + (warpM * 32 + mi * 16 + lr) * 36 + kb + 2 * lc;
                float2 v00 = *(const float2*)(p);
                float2 v10 = *(const float2*)(p + 8 * 36);
                float2 v01 = *(const float2*)(p + 8);
                float2 v11 = *(const float2*)(p + 8 * 36 + 8);
                bfsplit2(v00.x, v00.y, ah[mi][0], al[mi][0]);
                bfsplit2(v10.x, v10.y, ah[mi][1], al[mi][1]);
                bfsplit2(v01.x, v01.y, ah[mi][2], al[mi][2]);
                bfsplit2(v11.x, v11.y, ah[mi][3], al[mi][3]);
            }
            #pragma unroll
            for (int ni = 0; ni < 4; ++ni) {
                const float* p = Bs + (warpN * 32 + ni * 8 + lr) * 36 + kb + 2 * lc;
                float2 w0 = *(const float2*)(p);
                float2 w1 = *(const float2*)(p + 8);
                bfsplit2(w0.x, w0.y, bh[ni][0], bl[ni][0]);
                bfsplit2(w1.x, w1.y, bh[ni][1], bl[ni][1]);
            }
            #pragma unroll
            for (int mi = 0; mi < 2; ++mi)
                #pragma unroll
                for (int ni = 0; ni < 4; ++ni) {
                    mma_bf16(acc[mi][ni], ah[mi], bh[ni]);
                    mma_bf16(acc[mi][ni], ah[mi], bl[ni]);
                    mma_bf16(acc[mi][ni], al[mi], bh[ni]);
                }
        }
        __syncthreads();
    }

    rsacc += __shfl_xor_sync(0xffffffffu, rsacc, 1);
    if (rhalf == 0) {
        int gr = rowBase + rrow;
        if (gr < M) atomicAdd(&rowsum[gr], rsacc);
    }

    #pragma unroll
    for (int mi = 0; mi < 2; ++mi) {
        int r0 = rowBase + warpM * 32 + mi * 16 + lr;
        #pragma unroll
        for (int ni = 0; ni < 4; ++ni) {
            int gc = warpN * 32 + ni * 8 + lc * 2;
            if (gc >= N) continue;
            if (r0 < M)
                *(float2*)&C[(size_t)r0 * N + gc] = make_float2(acc[mi][ni][0], acc[mi][ni][1]);
            if (r0 + 8 < M)
                *(float2*)&C[(size_t)(r0 + 8) * N + gc] = make_float2(acc[mi][ni][2], acc[mi][ni][3]);
        }
    }
}

__global__ void reduce4_kernel(const float* __restrict__ part, float* __restrict__ outp, int n) {
    int i = blockIdx.x * blockDim.x + threadIdx.x;
    if (i < n) outp[i] = part[i] + part[i + n] + part[i + 2 * n] + part[i + 3 * n];
}

// ============================ small kernels ============================
__global__ void relu_kernel(const float* __restrict__ in, float* __restrict__ out, int n) {
    int i = blockIdx.x * blockDim.x + threadIdx.x;
    if (i < n) out[i] = fmaxf(in[i], 0.f);
}

__global__ void l2norm_split_f16(const float* __restrict__ in,
                                 fp16* __restrict__ oh, fp16* __restrict__ ol, int n) {
    int warp = (blockIdx.x * blockDim.x + threadIdx.x) >> 5;
    int lane = threadIdx.x & 31;
    if (warp >= n) return;
    float v0 = in[warp * 64 + lane];
    float v1 = in[warp * 64 + 32 + lane];
    float ss = v0 * v0 + v1 * v1;
    #pragma unroll
    for (int o = 16; o > 0; o >>= 1) ss += __shfl_xor_sync(0xffffffffu, ss, o);
    float inv = 1.f / fmaxf(sqrtf(ss), 1e-12f);
    fp16 h, l;
    splitf16(v0 * inv, h, l); oh[warp * 64 + lane] = h; ol[warp * 64 + lane] = l;
    splitf16(v1 * inv, h, l); oh[warp * 64 + 32 + lane] = h; ol[warp * 64 + 32 + lane] = l;
}

__global__ void g2_kernel(const float* __restrict__ vsum, const float* __restrict__ rowsum,
                          float* __restrict__ g2, int n) {
    int warp = (blockIdx.x * blockDim.x + threadIdx.x) >> 5;
    int lane = threadIdx.x & 31;
    if (warp >= n) return;
    float inv_rs = 1.f / rowsum[warp];
    float v0 = vsum[warp * 64 + lane] * inv_rs;
    float v1 = vsum[warp * 64 + 32 + lane] * inv_rs;
    float ss = v0 * v0 + v1 * v1;
    #pragma unroll
    for (int o = 16; o > 0; o >>= 1) ss += __shfl_xor_sync(0xffffffffu, ss, o);
    float inv = 1.f / fmaxf(sqrtf(ss), 1e-12f);
    v0 *= inv; v1 *= inv;
    g2[warp * 64 + lane] = 1.f / (1.f + expf(-v0));
    g2[warp * 64 + 32 + lane] = 1.f / (1.f + expf(-v1));
}

__global__ void disc_kernel(const float* __restrict__ emb1, const float* __restrict__ emb3,
                            const float* __restrict__ g2, const float* __restrict__ W,
                            const float* __restrict__ bptr, float* __restrict__ ret) {
    __shared__ float g2s[64];
    __shared__ float r1[64], r2[64];
    int r = blockIdx.x, t = threadIdx.x;
    g2s[t] = g2[r * 64 + t];
    __syncthreads();
    float u = 0.f;
    #pragma unroll
    for (int e = 0; e < 64; ++e) u += W[t * 64 + e] * g2s[e];
    r1[t] = emb1[r * 64 + t] * u;
    r2[t] = emb3[r * 64 + t] * u;
    __syncthreads();
    for (int s = 32; s > 0; s >>= 1) {
        if (t < s) { r1[t] += r1[t + s]; r2[t] += r2[t + s]; }
        __syncthreads();
    }
    if (t == 0) {
        float b = bptr[0];
        ret[r * 2 + 0] = r1[0] + b;
        ret[r * 2 + 1] = r2[0] + b;
    }
}

// ============================ host orchestration ============================
extern "C" void kernel_launch(void* const* d_in, const int* in_sizes, int n_in,
                              void* d_out, int out_size) {
    const float* feat     = (const float*)d_in[0];
    const float* feat_a   = (const float*)d_in[1];
    const float* feat_b   = (const float*)d_in[2];
    const int*   adj_rows = (const int*)  d_in[3];
    const int*   adj_cols = (const int*)  d_in[4];
    const float* adj_vals = (const float*)d_in[5];
    const float* graph_ng = (const float*)d_in[6];
    const float* W1       = (const float*)d_in[7];
    const float* W2       = (const float*)d_in[8];
    const float* Wd       = (const float*)d_in[9];
    const float* bd       = (const float*)d_in[10];
    const float* bn_gamma = (const float*)d_in[11];
    const float* bn_beta  = (const float*)d_in[12];
    const float* bn_mean  = (const float*)d_in[13];
    const float* bn_var   = (const float*)d_in[14];
    const float* Wpi      = (const float*)d_in[15];
    const float* bpi      = (const float*)d_in[16];
    const float* Wdisp    = (const float*)d_in[17];
    const float* bdisp    = (const float*)d_in[18];
    const float* Wmean    = (const float*)d_in[19];
    const float* bmean    = (const float*)d_in[20];
    const float* disc_W   = (const float*)d_in[21];
    const float* disc_b   = (const float*)d_in[22];

    float* out = (float*)d_out;
    float* o_z1   = out;
    float* o_pi   = out + 1920000;
    float* o_z3   = out + 1280000;
    float* o_rec  = out + 91920000;
    float* o_ret  = out + 191920000;

    float *s2, *emb1, *emb3, *vsum4, *vsum, *g2, *rowsum, *cval, *emb1t;
    int *cnt, *cur, *rowptr, *ccol;
    fp16 *s1, *fAh, *fAl, *w1t, *xdh, *xdl, *znh, *znl, *wzt;
    bf16 *hh, *hl, *z1h, *z1l, *w2th, *w2tl, *wdth, *wdtl;

    cudaGetSymbolAddress((void**)&s1, g_s1);
    cudaGetSymbolAddress((void**)&s2, g_s2);
    cudaGetSymbolAddress((void**)&emb1, g_emb1);
    cudaGetSymbolAddress((void**)&emb3, g_emb3);
    cudaGetSymbolAddress((void**)&vsum4, g_vsum4);
    cudaGetSymbolAddress((void**)&vsum, g_vsum);
    cudaGetSymbolAddress((void**)&g2,   g_g2);
    cudaGetSymbolAddress((void**)&rowsum, g_rowsum);
    cudaGetSymbolAddress((void**)&emb1t,  g_emb1t);
    cudaGetSymbolAddress((void**)&cnt,    g_cnt);
    cudaGetSymbolAddress((void**)&cur,    g_cur);
    cudaGetSymbolAddress((void**)&rowptr, g_rowptr);
    cudaGetSymbolAddress((void**)&ccol,   g_ccol);
    cudaGetSymbolAddress((void**)&cval,   g_cval);
    cudaGetSymbolAddress((void**)&fAh, g_fA_h); cudaGetSymbolAddress((void**)&fAl, g_fA_l);
    cudaGetSymbolAddress((void**)&w1t, g_w1t);
    cudaGetSymbolAddress((void**)&hh,  g_h_h);  cudaGetSymbolAddress((void**)&hl,  g_h_l);
    cudaGetSymbolAddress((void**)&z1h, g_z1_h); cudaGetSymbolAddress((void**)&z1l, g_z1_l);
    cudaGetSymbolAddress((void**)&xdh, g_xd_h); cudaGetSymbolAddress((void**)&xdl, g_xd_l);
    cudaGetSymbolAddress((void**)&znh, g_zn_h); cudaGetSymbolAddress((void**)&znl, g_zn_l);
    cudaGetSymbolAddress((void**)&w2th, g_w2t_h); cudaGetSymbolAddress((void**)&w2tl, g_w2t_l);
    cudaGetSymbolAddress((void**)&wdth, g_wdt_h); cudaGetSymbolAddress((void**)&wdtl, g_wdt_l);
    cudaGetSymbolAddress((void**)&wzt,  g_wzt);

    // ---- CSR build ----
    cudaMemsetAsync(cnt, 0, NN * sizeof(int));
    count_kernel<<<cdiv(NE, 256), 256>>>(adj_rows, cnt, NE);
    scan_kernel<<<1, 1024>>>(cnt, rowptr, NN);
    cudaMemsetAsync(cur, 0, NN * sizeof(int));
    scatter_kernel<<<cdiv(NE, 256), 256>>>(adj_rows, adj_cols, adj_vals,
                                           rowptr, cur, ccol, cval, NE);

    // ---- weight transpose + split / quant ----
    dim3 tb(32, 8);
    transpose_quant_f16<<<dim3(cdiv(H1D, 32), cdiv(FIN, 32)), tb>>>(W1, w1t, FIN, H1D, FIN);
    transpose_split_kernel<<<dim3(cdiv(H2D, 32), cdiv(H1D, 32)), tb>>>(W2, w2th, w2tl, H1D, H2D, LDH);
    transpose_split_kernel<<<dim3(cdiv(H1D, 32), cdiv(H2D, 32)), tb>>>(Wd, wdth, wdtl, H2D, H1D, H2D);
    const long long WZS = (long long)FIN * LDH;
    transpose_quant_f16<<<dim3(cdiv(FIN, 32), cdiv(H1D, 32)), tb>>>(Wpi,   wzt,           H1D, FIN, LDH);
    transpose_quant_f16<<<dim3(cdiv(FIN, 32), cdiv(H1D, 32)), tb>>>(Wdisp, wzt + WZS,     H1D, FIN, LDH);
    transpose_quant_f16<<<dim3(cdiv(FIN, 32), cdiv(H1D, 32)), tb>>>(Wmean, wzt + 2 * WZS, H1D, FIN, LDH);

    // ---- feats split upfront (fp16 2-plane, exact) ----
    const long long FAS = (long long)NN * FIN;
    split_f16_kernel<<<cdiv(NN * FIN / 4, 256), 256>>>(feat,   fAh,           fAl,           NN * FIN / 4);
    split_f16_kernel<<<cdiv(NN * FIN / 4, 256), 256>>>(feat_a, fAh + FAS,     fAl + FAS,     NN * FIN / 4);
    split_f16_kernel<<<cdiv(NN * FIN / 4, 256), 256>>>(feat_b, fAh + 2 * FAS, fAl + 2 * FAS, NN * FIN / 4);

    // ---- batched 3x GCN encode: GEMM1 fp16 2-term -> fp16 s1, GEMM2 bf16 3-term ----
    launch_t2<128, 7>(fAh, fAl, w1t, nullptr, s1, NN, H1D, FIN,
                      FIN, FIN, H1D, 3, FAS, 0, (long long)NN * H1D);
    agg_split_kernel<<<dim3(cdiv(H1D, 128), NN, 3), 128>>>(s1, hh, hl, rowptr, ccol, cval,
                                                           H1D, LDH, (long long)NN * H1D, (long long)NN * LDH);
    launch_tb<64, 0>(hh, hl, w2th, w2tl, s2, nullptr, nullptr, NN, H2D, H1D,
                     LDH, LDH, H2D, 3, (long long)NN * LDH, 0, (long long)NN * H2D);
    agg_kernel<<<dim3(1, NN, 3), 128>>>(s2, out, rowptr, ccol, cval, H2D, 0,
                                        (long long)NN * H2D, 640000LL);   // writes z1, z2, z3

    relu_kernel<<<cdiv(NN * H2D, 256), 256>>>(o_z1, emb1, NN * H2D);
    relu_kernel<<<cdiv(NN * H2D, 256), 256>>>(o_z3, emb3, NN * H2D);
    split_bf_kernel<<<cdiv(NN * H2D / 4, 256), 256>>>(o_z1, z1h, z1l, NN * H2D / 4);
    l2norm_split_f16<<<cdiv(NN, 8), 256>>>(o_z1, znh, znl, NN);

    // ---- ZINB decoder: hidden (bf16 3-term, writes fp16 planes), then batched fp16 2-term ----
    launch_tb<128, 1>(z1h, z1l, wdth, wdtl, nullptr, xdh, xdl, NN, H1D, H2D,
                      H2D, H2D, LDH, 1, 0, 0, 0, bd, bn_gamma, bn_beta, bn_mean, bn_var);
    launch_t2<128, 6>(xdh, xdl, wzt, o_pi, nullptr, NN, FIN, H1D,
                      LDH, LDH, FIN, 3, 0, WZS, 30000000LL, bpi, bdisp, bmean);

    // ---- adjacency reconstruction: sigmoid(zn @ zn^T), fp16 2-term ----
    launch_t2<128, 5>(znh, znl, znh, o_rec, nullptr, NN, NN, H2D,
                      H2D, H2D, NN, 1, 0, 0, 0);

    // ---- readout (split-K GEMM + fused rowsum) + discriminator ----
    cudaMemsetAsync(rowsum, 0, NN * sizeof(float));
    transpose_kernel<<<dim3(cdiv(H2D, 32), cdiv(NN, 32)), tb>>>(emb1, emb1t, NN, H2D);
    {
        constexpr int SMEMSZ = STAGES * 192 * ROWB;
        cudaFuncSetAttribute(tgemm64sk, cudaFuncAttributeMaxDynamicSharedMemorySize, SMEMSZ);
        dim3 grid(1, cdiv(NN, 128), 4);
        tgemm64sk<<<grid, 256, SMEMSZ>>>(graph_ng, emb1t, vsum4, rowsum, NN, H2D, NN);
    }
    reduce4_kernel<<<cdiv(NN * H2D, 256), 256>>>(vsum4, vsum, NN * H2D);
    g2_kernel<<<cdiv(NN, 8), 256>>>(vsum, rowsum, g2, NN);
    disc_kernel<<<NN, 64>>>(emb1, emb3, g2, disc_W, disc_b, o_ret);
}

// round 16
// speedup vs baseline: 1.1167x; 1.0957x over previous
#include <cuda_runtime.h>
#include <cuda_bf16.h>
#include <cuda_fp16.h>
#include <math.h>
#include <stdint.h>

// Problem constants (fixed by the reference)
#define NN   10000
#define FIN  3000
#define H1D  500
#define H2D  64
#define NE   160000
#define BN_EPS 1e-5f
#define LDH  512           // padded leading dim for K=500 operands (16B-aligned rows)

static inline int cdiv(int a, int b) { return (a + b - 1) / b; }

typedef __nv_bfloat16 bf16;
typedef __half fp16;

// ============================ device scratch ============================
__device__ fp16  g_s1[3 * NN * H1D];      // batched GEMM1 out (fp16 storage)
__device__ float g_s2[3 * NN * H2D];
__device__ float g_emb1[NN * H2D];
__device__ float g_emb3[NN * H2D];
__device__ float g_vsum4[4 * NN * H2D];
__device__ float g_vsum[NN * H2D];
__device__ float g_g2[NN * H2D];
__device__ float g_rowsum[NN];
__device__ float g_emb1t[H2D * NN];
__device__ int   g_cnt[NN];
__device__ int   g_cur[NN];
__device__ int   g_rowptr[NN + 1];
__device__ int   g_ccol[NE];
__device__ float g_cval[NE];
// fp16 2-term path: encoder GEMM1
__device__ fp16 g_fA_h[3 * NN * FIN],  g_fA_l[3 * NN * FIN];
__device__ fp16 g_w1t[H1D * FIN];
// bf16 3-term path: GEMM2 + Wd
__device__ bf16 g_h_h [3 * NN * LDH],  g_h_l [3 * NN * LDH];
__device__ bf16 g_z1_h[NN * H2D],  g_z1_l[NN * H2D];
__device__ bf16 g_w2t_h[H2D * LDH], g_w2t_l[H2D * LDH];
__device__ bf16 g_wdt_h[H1D * H2D], g_wdt_l[H1D * H2D];
// fp16 paths: decoder (1-term) + rec_adj (2-term)
__device__ fp16 g_xd_h[NN * LDH];
__device__ fp16 g_zn_h[NN * H2D],  g_zn_l[NN * H2D];
__device__ fp16 g_wzt[3 * FIN * LDH];

// ============================ CSR build ============================
__global__ void count_kernel(const int* __restrict__ rows, int* __restrict__ cnt, int e) {
    int i = blockIdx.x * blockDim.x + threadIdx.x;
    if (i < e) atomicAdd(&cnt[rows[i]], 1);
}

__global__ void scan_kernel(const int* __restrict__ cnt, int* __restrict__ rowptr, int n) {
    __shared__ int sums[1024];
    const int PER = 10;
    int tid = threadIdx.x;
    int base = tid * PER;
    int local[PER];
    int s = 0;
    #pragma unroll
    for (int i = 0; i < PER; ++i) {
        int idx = base + i;
        int v = (idx < n) ? cnt[idx] : 0;
        local[i] = s;
        s += v;
    }
    sums[tid] = s;
    __syncthreads();
    for (int off = 1; off < 1024; off <<= 1) {
        int v = (tid >= off) ? sums[tid - off] : 0;
        __syncthreads();
        sums[tid] += v;
        __syncthreads();
    }
    int offset = (tid > 0) ? sums[tid - 1] : 0;
    #pragma unroll
    for (int i = 0; i < PER; ++i) {
        int idx = base + i;
        if (idx < n) rowptr[idx] = offset + local[i];
    }
    if (tid == 1023) rowptr[n] = sums[1023];
}

__global__ void scatter_kernel(const int* __restrict__ rows, const int* __restrict__ cols,
                               const float* __restrict__ vals,
                               const int* __restrict__ rowptr, int* __restrict__ cur,
                               int* __restrict__ ccol, float* __restrict__ cval, int e) {
    int i = blockIdx.x * blockDim.x + threadIdx.x;
    if (i < e) {
        int r = rows[i];
        int p = rowptr[r] + atomicAdd(&cur[r], 1);
        ccol[p] = cols[i];
        cval[p] = vals[i];
    }
}

// ============================ splits ============================
__device__ __forceinline__ void splitf(float v, bf16& h, bf16& l) {
    h = __float2bfloat16(v);
    l = __float2bfloat16(v - __bfloat162float(h));
}
__device__ __forceinline__ void splitf16(float v, fp16& h, fp16& l) {
    h = __float2half_rn(v);
    l = __float2half_rn(v - __half2float(h));
}

__global__ void split_f16_kernel(const float* __restrict__ in, fp16* __restrict__ hi,
                                 fp16* __restrict__ lo, int n4) {
    int i = blockIdx.x * blockDim.x + threadIdx.x;
    if (i >= n4) return;
    float4 v = ((const float4*)in)[i];
    fp16 h0, l0, h1, l1, h2, l2, h3, l3;
    splitf16(v.x, h0, l0); splitf16(v.y, h1, l1);
    splitf16(v.z, h2, l2); splitf16(v.w, h3, l3);
    ((ushort4*)hi)[i] = make_ushort4(__half_as_ushort(h0), __half_as_ushort(h1),
                                     __half_as_ushort(h2), __half_as_ushort(h3));
    ((ushort4*)lo)[i] = make_ushort4(__half_as_ushort(l0), __half_as_ushort(l1),
                                     __half_as_ushort(l2), __half_as_ushort(l3));
}

__global__ void split_bf_kernel(const float* __restrict__ in, bf16* __restrict__ hi,
                                bf16* __restrict__ lo, int n4) {
    int i = blockIdx.x * blockDim.x + threadIdx.x;
    if (i >= n4) return;
    float4 v = ((const float4*)in)[i];
    bf16 h0, l0, h1, l1, h2, l2, h3, l3;
    splitf(v.x, h0, l0); splitf(v.y, h1, l1);
    splitf(v.z, h2, l2); splitf(v.w, h3, l3);
    ((ushort4*)hi)[i] = make_ushort4(__bfloat16_as_ushort(h0), __bfloat16_as_ushort(h1),
                                     __bfloat16_as_ushort(h2), __bfloat16_as_ushort(h3));
    ((ushort4*)lo)[i] = make_ushort4(__bfloat16_as_ushort(l0), __bfloat16_as_ushort(l1),
                                     __bfloat16_as_ushort(l2), __bfloat16_as_ushort(l3));
}

__global__ void transpose_split_kernel(const float* __restrict__ in,
                                       bf16* __restrict__ outh, bf16* __restrict__ outl,
                                       int R, int C, int LDO) {
    __shared__ float t[32][33];
    int c0 = blockIdx.x * 32, r0 = blockIdx.y * 32;
    int x = threadIdx.x, y = threadIdx.y;
    #pragma unroll
    for (int j = 0; j < 32; j += 8) {
        int r = r0 + y + j, c = c0 + x;
        if (r < R && c < C) t[y + j][x] = in[(size_t)r * C + c];
    }
    __syncthreads();
    #pragma unroll
    for (int j = 0; j < 32; j += 8) {
        int r = c0 + y + j, c = r0 + x;
        if (r < C && c < R) {
            bf16 h, l;
            splitf(t[x][y + j], h, l);
            outh[(size_t)r * LDO + c] = h;
            outl[(size_t)r * LDO + c] = l;
        }
    }
}

__global__ void transpose_quant_f16(const float* __restrict__ in, fp16* __restrict__ outp,
                                    int R, int C, int LDO) {
    __shared__ float t[32][33];
    int c0 = blockIdx.x * 32, r0 = blockIdx.y * 32;
    int x = threadIdx.x, y = threadIdx.y;
    #pragma unroll
    for (int j = 0; j < 32; j += 8) {
        int r = r0 + y + j, c = c0 + x;
        if (r < R && c < C) t[y + j][x] = in[(size_t)r * C + c];
    }
    __syncthreads();
    #pragma unroll
    for (int j = 0; j < 32; j += 8) {
        int r = c0 + y + j, c = r0 + x;
        if (r < C && c < R) outp[(size_t)r * LDO + c] = __float2half_rn(t[x][y + j]);
    }
}

__global__ void transpose_kernel(const float* __restrict__ in, float* __restrict__ out, int R, int C) {
    __shared__ float t[32][33];
    int c0 = blockIdx.x * 32, r0 = blockIdx.y * 32;
    int x = threadIdx.x, y = threadIdx.y;
    #pragma unroll
    for (int j = 0; j < 32; j += 8) {
        int r = r0 + y + j, c = c0 + x;
        if (r < R && c < C) t[y + j][x] = in[(size_t)r * C + c];
    }
    __syncthreads();
    #pragma unroll
    for (int j = 0; j < 32; j += 8) {
        int r = c0 + y + j, c = r0 + x;
        if (r < C && c < R) out[(size_t)r * R + c] = t[x][y + j];
    }
}

// ============================ sparse aggregation (batched via grid.z) ============================
__global__ void agg_kernel(const float* __restrict__ src, float* __restrict__ dst,
                           const int* __restrict__ rowptr, const int* __restrict__ ccol,
                           const float* __restrict__ cval, int width, int do_relu,
                           long long zsrc, long long zdst) {
    src += (long long)blockIdx.z * zsrc;
    dst += (long long)blockIdx.z * zdst;
    int r = blockIdx.y;
    int col = blockIdx.x * 128 + threadIdx.x;
    if (col >= width) return;
    int s = rowptr[r], e = rowptr[r + 1];
    float acc = 0.f;
    for (int j = s; j < e; ++j) {
        acc += cval[j] * src[(long long)ccol[j] * width + col];
    }
    if (do_relu) acc = fmaxf(acc, 0.f);
    dst[(long long)r * width + col] = acc;
}

// agg + relu -> bf16 hi/lo planes; src is fp16
__global__ void agg_split_kernel(const fp16* __restrict__ src,
                                 bf16* __restrict__ dh, bf16* __restrict__ dl,
                                 const int* __restrict__ rowptr, const int* __restrict__ ccol,
                                 const float* __restrict__ cval, int width, int ldo,
                                 long long zsrc, long long zdst) {
    src += (long long)blockIdx.z * zsrc;
    dh  += (long long)blockIdx.z * zdst;
    dl  += (long long)blockIdx.z * zdst;
    int r = blockIdx.y;
    int col = blockIdx.x * 128 + threadIdx.x;
    if (col >= width) return;
    int s = rowptr[r], e = rowptr[r + 1];
    float acc = 0.f;
    for (int j = s; j < e; ++j) {
        acc += cval[j] * __half2float(src[(long long)ccol[j] * width + col]);
    }
    acc = fmaxf(acc, 0.f);
    bf16 h, l;
    splitf(acc, h, l);
    dh[(long long)r * ldo + col] = h;
    dl[(long long)r * ldo + col] = l;
}

// ============================ epilogue ============================
template <int MODE>
__device__ __forceinline__ float epi(float v, int gc,
                                     const float* p1, const float* p2, const float* p3,
                                     const float* p4, const float* p5) {
    if (MODE == 1) {
        v += __ldg(p1 + gc);
        v = __ldg(p2 + gc) * (v - __ldg(p4 + gc)) * rsqrtf(__ldg(p5 + gc) + BN_EPS) + __ldg(p3 + gc);
        v = fmaxf(v, 0.f);
    } else if (MODE == 2) {
        v += __ldg(p1 + gc);
        v = 1.f / (1.f + expf(-v));
    } else if (MODE == 3) {
        v += __ldg(p1 + gc);
        v = fmaxf(v, 0.f) + log1pf(expf(-fabsf(v)));
        v = fminf(fmaxf(v, 1e-4f), 1e4f);
    } else if (MODE == 4) {
        v += __ldg(p1 + gc);
        v = expf(v);
        v = fminf(fmaxf(v, 1e-5f), 1e6f);
    } else if (MODE == 5) {
        v = 1.f / (1.f + expf(-v));
    }
    return v;   // MODE 0 / 7: identity
}

template <int MODE>
__device__ __forceinline__ float epi_sel(int bz, float v, int gc,
                                         const float* p1, const float* p2, const float* p3,
                                         const float* p4, const float* p5) {
    if (MODE != 6) return epi<MODE>(v, gc, p1, p2, p3, p4, p5);
    if (bz == 0) return epi<2>(v, gc, p1, nullptr, nullptr, nullptr, nullptr);
    if (bz == 1) return epi<3>(v, gc, p2, nullptr, nullptr, nullptr, nullptr);
    return epi<4>(v, gc, p3, nullptr, nullptr, nullptr, nullptr);
}

// ============================ MMA / LDSM helpers ============================
__device__ __forceinline__ void mma_bf16(float* d, const uint32_t* a, const uint32_t* b) {
    asm volatile(
        "mma.sync.aligned.m16n8k16.row.col.f32.bf16.bf16.f32 "
        "{%0,%1,%2,%3}, {%4,%5,%6,%7}, {%8,%9}, {%0,%1,%2,%3};"
        : "+f"(d[0]), "+f"(d[1]), "+f"(d[2]), "+f"(d[3])
        : "r"(a[0]), "r"(a[1]), "r"(a[2]), "r"(a[3]), "r"(b[0]), "r"(b[1]));
}
__device__ __forceinline__ void mma_f16(float* d, const uint32_t* a, const uint32_t* b) {
    asm volatile(
        "mma.sync.aligned.m16n8k16.row.col.f32.f16.f16.f32 "
        "{%0,%1,%2,%3}, {%4,%5,%6,%7}, {%8,%9}, {%0,%1,%2,%3};"
        : "+f"(d[0]), "+f"(d[1]), "+f"(d[2]), "+f"(d[3])
        : "r"(a[0]), "r"(a[1]), "r"(a[2]), "r"(a[3]), "r"(b[0]), "r"(b[1]));
}
__device__ __forceinline__ void ldsm_x4(uint32_t& r0, uint32_t& r1, uint32_t& r2, uint32_t& r3,
                                        uint32_t addr) {
    asm volatile("ldmatrix.sync.aligned.m8n8.x4.shared.b16 {%0,%1,%2,%3}, [%4];"
                 : "=r"(r0), "=r"(r1), "=r"(r2), "=r"(r3) : "r"(addr));
}

__device__ __forceinline__ void bfsplit2(float x, float y, uint32_t& hi, uint32_t& lo) {
    uint32_t h;
    asm("cvt.rn.bf16x2.f32 %0, %1, %2;" : "=r"(h) : "f"(y), "f"(x));
    float xh = __uint_as_float(h << 16);
    float yh = __uint_as_float(h & 0xffff0000u);
    float xl = x - xh;
    float yl = y - yh;
    uint32_t l;
    asm("cvt.rn.bf16x2.f32 %0, %1, %2;" : "=r"(l) : "f"(yl), "f"(xl));
    hi = h; lo = l;
}

__device__ __forceinline__ void cp_async16(uint32_t saddr, const void* gaddr, int src_size) {
    asm volatile("cp.async.cg.shared.global [%0], [%1], 16, %2;"
                 :: "r"(saddr), "l"(gaddr), "r"(src_size) : "memory");
}

__device__ __forceinline__ uint32_t smem_u32(const void* p) {
    uint32_t a;
    asm("{ .reg .u64 t; cvta.to.shared.u64 t, %1; cvt.u32.u64 %0, t; }" : "=r"(a) : "l"(p));
    return a;
}

// ============================ bf16 3-term GEMM (batched, ldmatrix, 2-stage) ============================
#define BROWB 80

template <int NT>
__device__ __forceinline__ void load_stage_bf(const bf16* __restrict__ Ah, const bf16* __restrict__ Al,
                                              const bf16* __restrict__ Bh, const bf16* __restrict__ Bl,
                                              int M, int N, int K, int lda, int ldb,
                                              int rowBase, int colBase, int k0,
                                              uint32_t sb, int tid) {
    #pragma unroll
    for (int i = 0; i < 2; ++i) {
        int idx = tid + i * 256;
        int row = idx >> 2, c = idx & 3;
        int gr = rowBase + row, gk = k0 + c * 8;
        int sz = 0;
        if (gr < M) { int rem = (K - gk) * 2; sz = rem >= 16 ? 16 : (rem > 0 ? rem : 0); }
        uint32_t off = row * BROWB + c * 16;
        cp_async16(sb + off, Ah + (size_t)gr * lda + gk, sz);
        cp_async16(sb + 128 * BROWB + off, Al + (size_t)gr * lda + gk, sz);
    }
    uint32_t bbase = sb + 2 * 128 * BROWB;
    #pragma unroll
    for (int i = 0; i < NT / 64; ++i) {
        int idx = tid + i * 256;
        int row = idx >> 2, c = idx & 3;
        int gn = colBase + row, gk = k0 + c * 8;
        int sz = 0;
        if (gn < N) { int rem = (K - gk) * 2; sz = rem >= 16 ? 16 : (rem > 0 ? rem : 0); }
        uint32_t off = row * BROWB + c * 16;
        cp_async16(bbase + off, Bh + (size_t)gn * ldb + gk, sz);
        cp_async16(bbase + NT * BROWB + off, Bl + (size_t)gn * ldb + gk, sz);
    }
}

template <int NT, int MODE>
__global__ void __launch_bounds__(256, 2)
tb_gemm(const bf16* __restrict__ Ah, const bf16* __restrict__ Al,
        const bf16* __restrict__ Bh, const bf16* __restrict__ Bl,
        float* __restrict__ C, fp16* __restrict__ Ch,
        int M, int N, int K, int lda, int ldb, int ldc,
        long long strideA, long long strideB, long long strideC,
        const float* __restrict__ p1, const float* __restrict__ p2,
        const float* __restrict__ p3, const float* __restrict__ p4,
        const float* __restrict__ p5) {
    constexpr int STAGEB = (256 + 2 * NT) * BROWB;
    constexpr int NMI = (NT == 128) ? 4 : 2;
    const int bz = blockIdx.z;
    Ah += (long long)bz * strideA; Al += (long long)bz * strideA;
    Bh += (long long)bz * strideB; Bl += (long long)bz * strideB;
    if (C)  C  += (long long)bz * strideC;
    if (Ch) Ch += (long long)bz * strideC;

    extern __shared__ char smc[];
    uint32_t sbase = smem_u32(smc);
    const int tid = threadIdx.x;
    const int wid = tid >> 5, lane = tid & 31;
    const int warpM = (NT == 128) ? (wid & 1) : (wid & 3);
    const int warpN = (NT == 128) ? (wid >> 1) : (wid >> 2);
    const int mtile = (NT == 128) ? 64 : 32;
    const int rowBase = blockIdx.y * 128;
    const int colBase = blockIdx.x * NT;
    const int nt = (K + 31) >> 5;
    const int lr = lane >> 2, lc = lane & 3;
    const int lrow = lane & 7;

    uint32_t a_off[NMI], b_off[2];
    #pragma unroll
    for (int mi = 0; mi < NMI; ++mi)
        a_off[mi] = (uint32_t)((warpM * mtile + mi * 16 + ((lane >> 3) & 1) * 8 + lrow) * BROWB
                               + (lane >> 4) * 16);
    #pragma unroll
    for (int pr = 0; pr < 2; ++pr)
        b_off[pr] = (uint32_t)((warpN * 32 + pr * 16 + (lane >> 4) * 8 + lrow) * BROWB
                               + ((lane >> 3) & 1) * 16);

    float acc[NMI][4][4];
    #pragma unroll
    for (int i = 0; i < NMI; ++i)
        #pragma unroll
        for (int j = 0; j < 4; ++j)
            #pragma unroll
            for (int k = 0; k < 4; ++k) acc[i][j][k] = 0.f;

    load_stage_bf<NT>(Ah, Al, Bh, Bl, M, N, K, lda, ldb, rowBase, colBase, 0, sbase, tid);
    asm volatile("cp.async.commit_group;" ::: "memory");

    for (int t = 0; t < nt; ++t) {
        if (t + 1 < nt) {
            load_stage_bf<NT>(Ah, Al, Bh, Bl, M, N, K, lda, ldb, rowBase, colBase, (t + 1) << 5,
                              sbase + ((t + 1) & 1) * STAGEB, tid);
            asm volatile("cp.async.commit_group;" ::: "memory");
            asm volatile("cp.async.wait_group 1;" ::: "memory");
        } else {
            asm volatile("cp.async.wait_group 0;" ::: "memory");
        }
        __syncthreads();

        uint32_t sA_u = sbase + (t & 1) * STAGEB;
        uint32_t sB_u = sA_u + 2 * 128 * BROWB;

        #pragma unroll
        for (int kb = 0; kb < 2; ++kb) {
            uint32_t kb2 = kb * 32;
            uint32_t ah[NMI][4], al[NMI][4], bh[4][2], bl[4][2];
            #pragma unroll
            for (int mi = 0; mi < NMI; ++mi) {
                ldsm_x4(ah[mi][0], ah[mi][1], ah[mi][2], ah[mi][3], sA_u + a_off[mi] + kb2);
                ldsm_x4(al[mi][0], al[mi][1], al[mi][2], al[mi][3],
                        sA_u + 128 * BROWB + a_off[mi] + kb2);
            }
            #pragma unroll
            for (int pr = 0; pr < 2; ++pr) {
                ldsm_x4(bh[pr * 2][0], bh[pr * 2][1], bh[pr * 2 + 1][0], bh[pr * 2 + 1][1],
                        sB_u + b_off[pr] + kb2);
                ldsm_x4(bl[pr * 2][0], bl[pr * 2][1], bl[pr * 2 + 1][0], bl[pr * 2 + 1][1],
                        sB_u + NT * BROWB + b_off[pr] + kb2);
            }
            #pragma unroll
            for (int mi = 0; mi < NMI; ++mi)
                #pragma unroll
                for (int ni = 0; ni < 4; ++ni) {
                    mma_bf16(acc[mi][ni], ah[mi], bh[ni]);
                    mma_bf16(acc[mi][ni], ah[mi], bl[ni]);
                    mma_bf16(acc[mi][ni], al[mi], bh[ni]);
                }
        }
        __syncthreads();
    }

    #pragma unroll
    for (int mi = 0; mi < NMI; ++mi) {
        int r0 = rowBase + warpM * mtile + mi * 16 + lr;
        #pragma unroll
        for (int ni = 0; ni < 4; ++ni) {
            int gc = colBase + warpN * 32 + ni * 8 + lc * 2;
            if (gc >= N) continue;
            #pragma unroll
            for (int half = 0; half < 2; ++half) {
                int gr = r0 + half * 8;
                if (gr >= M) continue;
                float vx = epi_sel<MODE>(bz, acc[mi][ni][half * 2 + 0], gc,     p1, p2, p3, p4, p5);
                float vy = epi_sel<MODE>(bz, acc[mi][ni][half * 2 + 1], gc + 1, p1, p2, p3, p4, p5);
                if (MODE == 1) {
                    __half2 hv = __floats2half2_rn(vx, vy);
                    *(__half2*)&Ch[(size_t)gr * ldc + gc] = hv;
                } else {
                    *(float2*)&C[(size_t)gr * ldc + gc] = make_float2(vx, vy);
                }
            }
        }
    }
}

template <int NT, int MODE>
static void launch_tb(const bf16* Ah, const bf16* Al, const bf16* Bh, const bf16* Bl,
                      float* C, fp16* Ch, int M, int N, int K,
                      int lda, int ldb, int ldc, int nz,
                      long long sA, long long sB, long long sC,
                      const float* p1 = nullptr, const float* p2 = nullptr,
                      const float* p3 = nullptr, const float* p4 = nullptr,
                      const float* p5 = nullptr) {
    constexpr int SMEMSZ = 2 * (256 + 2 * NT) * BROWB;
    cudaFuncSetAttribute(tb_gemm<NT, MODE>, cudaFuncAttributeMaxDynamicSharedMemorySize, SMEMSZ);
    dim3 grid(cdiv(N, NT), cdiv(M, 128), nz);
    tb_gemm<NT, MODE><<<grid, 256, SMEMSZ>>>(Ah, Al, Bh, Bl, C, Ch, M, N, K,
                                             lda, ldb, ldc, sA, sB, sC, p1, p2, p3, p4, p5);
}

// ============================ fp16 GEMM (ldmatrix, 2-stage, 1 or 2 A-planes) ============================
// TWO=true:  D = (Ah + Al) @ Bh^T   TWO=false: D = Ah @ Bh^T
// MODE 7: write raw fp16 to C16. Other modes: float C.
template <int NT, bool TWO>
__device__ __forceinline__ void load_stage_f16(const fp16* __restrict__ Ah, const fp16* __restrict__ Al,
                                               const fp16* __restrict__ Bh,
                                               int M, int N, int K, int lda, int ldb,
                                               int rowBase, int colBase, int k0,
                                               uint32_t sb, int tid) {
    constexpr int APL = TWO ? 2 : 1;
    #pragma unroll
    for (int i = 0; i < 2; ++i) {
        int idx = tid + i * 256;
        int row = idx >> 2, c = idx & 3;
        int gr = rowBase + row, gk = k0 + c * 8;
        int sz = 0;
        if (gr < M) { int rem = (K - gk) * 2; sz = rem >= 16 ? 16 : (rem > 0 ? rem : 0); }
        uint32_t off = row * BROWB + c * 16;
        cp_async16(sb + off, Ah + (size_t)gr * lda + gk, sz);
        if (TWO) cp_async16(sb + 128 * BROWB + off, Al + (size_t)gr * lda + gk, sz);
    }
    uint32_t bbase = sb + APL * 128 * BROWB;
    #pragma unroll
    for (int i = 0; i < NT / 64; ++i) {
        int idx = tid + i * 256;
        int row = idx >> 2, c = idx & 3;
        int gn = colBase + row, gk = k0 + c * 8;
        int sz = 0;
        if (gn < N) { int rem = (K - gk) * 2; sz = rem >= 16 ? 16 : (rem > 0 ? rem : 0); }
        uint32_t off = row * BROWB + c * 16;
        cp_async16(bbase + off, Bh + (size_t)gn * ldb + gk, sz);
    }
}

template <int NT, int MODE, bool TWO>
__global__ void __launch_bounds__(256, 2)
t2_gemm(const fp16* __restrict__ Ah, const fp16* __restrict__ Al,
        const fp16* __restrict__ Bh,
        float* __restrict__ C, fp16* __restrict__ C16,
        int M, int N, int K, int lda, int ldb, int ldc,
        long long strideA, long long strideB, long long strideC,
        const float* __restrict__ p1, const float* __restrict__ p2,
        const float* __restrict__ p3, const float* __restrict__ p4,
        const float* __restrict__ p5) {
    constexpr int APL = TWO ? 2 : 1;
    constexpr int STAGEB = (APL * 128 + NT) * BROWB;
    constexpr int NMI = (NT == 128) ? 4 : 2;
    const int bz = blockIdx.z;
    Ah += (long long)bz * strideA;
    if (TWO) Al += (long long)bz * strideA;
    Bh += (long long)bz * strideB;
    if (C)   C   += (long long)bz * strideC;
    if (C16) C16 += (long long)bz * strideC;

    extern __shared__ char smc[];
    uint32_t sbase = smem_u32(smc);
    const int tid = threadIdx.x;
    const int wid = tid >> 5, lane = tid & 31;
    const int warpM = (NT == 128) ? (wid & 1) : (wid & 3);
    const int warpN = (NT == 128) ? (wid >> 1) : (wid >> 2);
    const int mtile = (NT == 128) ? 64 : 32;
    const int rowBase = blockIdx.y * 128;
    const int colBase = blockIdx.x * NT;
    const int nt = (K + 31) >> 5;
    const int lr = lane >> 2, lc = lane & 3;
    const int lrow = lane & 7;

    uint32_t a_off[NMI], b_off[2];
    #pragma unroll
    for (int mi = 0; mi < NMI; ++mi)
        a_off[mi] = (uint32_t)((warpM * mtile + mi * 16 + ((lane >> 3) & 1) * 8 + lrow) * BROWB
                               + (lane >> 4) * 16);
    #pragma unroll
    for (int pr = 0; pr < 2; ++pr)
        b_off[pr] = (uint32_t)((warpN * 32 + pr * 16 + (lane >> 4) * 8 + lrow) * BROWB
                               + ((lane >> 3) & 1) * 16);

    float acc[NMI][4][4];
    #pragma unroll
    for (int i = 0; i < NMI; ++i)
        #pragma unroll
        for (int j = 0; j < 4; ++j)
            #pragma unroll
            for (int k = 0; k < 4; ++k) acc[i][j][k] = 0.f;

    load_stage_f16<NT, TWO>(Ah, Al, Bh, M, N, K, lda, ldb, rowBase, colBase, 0, sbase, tid);
    asm volatile("cp.async.commit_group;" ::: "memory");

    for (int t = 0; t < nt; ++t) {
        if (t + 1 < nt) {
            load_stage_f16<NT, TWO>(Ah, Al, Bh, M, N, K, lda, ldb, rowBase, colBase, (t + 1) << 5,
                                    sbase + ((t + 1) & 1) * STAGEB, tid);
            asm volatile("cp.async.commit_group;" ::: "memory");
            asm volatile("cp.async.wait_group 1;" ::: "memory");
        } else {
            asm volatile("cp.async.wait_group 0;" ::: "memory");
        }
        __syncthreads();

        uint32_t sA_u = sbase + (t & 1) * STAGEB;
        uint32_t sB_u = sA_u + APL * 128 * BROWB;

        #pragma unroll
        for (int kb = 0; kb < 2; ++kb) {
            uint32_t kb2 = kb * 32;
            uint32_t ah[NMI][4], al[NMI][4], bh[4][2];
            #pragma unroll
            for (int mi = 0; mi < NMI; ++mi) {
                ldsm_x4(ah[mi][0], ah[mi][1], ah[mi][2], ah[mi][3], sA_u + a_off[mi] + kb2);
                if (TWO)
                    ldsm_x4(al[mi][0], al[mi][1], al[mi][2], al[mi][3],
                            sA_u + 128 * BROWB + a_off[mi] + kb2);
            }
            #pragma unroll
            for (int pr = 0; pr < 2; ++pr) {
                ldsm_x4(bh[pr * 2][0], bh[pr * 2][1], bh[pr * 2 + 1][0], bh[pr * 2 + 1][1],
                        sB_u + b_off[pr] + kb2);
            }
            #pragma unroll
            for (int mi = 0; mi < NMI; ++mi)
                #pragma unroll
                for (int ni = 0; ni < 4; ++ni) {
                    mma_f16(acc[mi][ni], ah[mi], bh[ni]);
                    if (TWO) mma_f16(acc[mi][ni], al[mi], bh[ni]);
                }
        }
        __syncthreads();
    }

    #pragma unroll
    for (int mi = 0; mi < NMI; ++mi) {
        int r0 = rowBase + warpM * mtile + mi * 16 + lr;
        #pragma unroll
        for (int ni = 0; ni < 4; ++ni) {
            int gc = colBase + warpN * 32 + ni * 8 + lc * 2;
            if (gc >= N) continue;
            #pragma unroll
            for (int half = 0; half < 2; ++half) {
                int gr = r0 + half * 8;
                if (gr >= M) continue;
                float vx = epi_sel<MODE>(bz, acc[mi][ni][half * 2 + 0], gc,     p1, p2, p3, p4, p5);
                float vy = epi_sel<MODE>(bz, acc[mi][ni][half * 2 + 1], gc + 1, p1, p2, p3, p4, p5);
                if (MODE == 7) {
                    __half2 hv = __floats2half2_rn(vx, vy);
                    *(__half2*)&C16[(size_t)gr * ldc + gc] = hv;
                } else {
                    *(float2*)&C[(size_t)gr * ldc + gc] = make_float2(vx, vy);
                }
            }
        }
    }
}

template <int NT, int MODE, bool TWO>
static void launch_t2(const fp16* Ah, const fp16* Al, const fp16* Bh,
                      float* C, fp16* C16, int M, int N, int K,
                      int lda, int ldb, int ldc, int nz,
                      long long sA, long long sB, long long sC,
                      const float* p1 = nullptr, const float* p2 = nullptr,
                      const float* p3 = nullptr, const float* p4 = nullptr,
                      const float* p5 = nullptr) {
    constexpr int SMEMSZ = 2 * ((TWO ? 256 : 128) + NT) * BROWB;
    cudaFuncSetAttribute(t2_gemm<NT, MODE, TWO>, cudaFuncAttributeMaxDynamicSharedMemorySize, SMEMSZ);
    dim3 grid(cdiv(N, NT), cdiv(M, 128), nz);
    t2_gemm<NT, MODE, TWO><<<grid, 256, SMEMSZ>>>(Ah, Al, Bh, C, C16, M, N, K,
                                                  lda, ldb, ldc, sA, sB, sC, p1, p2, p3, p4, p5);
}

// ============================ fp32 split-K GEMM + fused rowsum (readout) ============================
#define STAGES 3
#define ROWB 144
#define NCHUNK 313
#define CPZ 79

__device__ __forceinline__ void load_stage_f64(const float* __restrict__ A, const float* __restrict__ Bt,
                                               int M, int N, int K, int rowBase, int k0,
                                               uint32_t sA, int tid) {
    #pragma unroll
    for (int i = 0; i < 4; ++i) {
        int idx = tid + i * 256;
        int row = idx >> 3, c4 = idx & 7;
        int gr = rowBase + row, gk = k0 + c4 * 4;
        int sz = (gr < M && gk < K) ? 16 : 0;
        cp_async16(sA + row * ROWB + c4 * 16, A + (size_t)gr * K + gk, sz);
    }
    uint32_t sB = sA + 128 * ROWB;
    #pragma unroll
    for (int i = 0; i < 2; ++i) {
        int idx = tid + i * 256;
        int row = idx >> 3, c4 = idx & 7;
        int gn = row, gk = k0 + c4 * 4;
        int sz = (gn < N && gk < K) ? 16 : 0;
        cp_async16(sB + row * ROWB + c4 * 16, Bt + (size_t)gn * K + gk, sz);
    }
}

__global__ void __launch_bounds__(256, 2)
tgemm64sk(const float* __restrict__ A, const float* __restrict__ Bt,
          float* __restrict__ Cpart, float* __restrict__ rowsum,
          int M, int N, int K) {
    constexpr int STAGEB = 192 * ROWB;
    extern __shared__ float sm[];
    uint32_t sbase = smem_u32(sm);
    const int tid = threadIdx.x;
    const int wid = tid >> 5, lane = tid & 31;
    const int warpM = wid & 3, warpN = wid >> 2;
    const int rowBase = blockIdx.y * 128;
    const int zz = blockIdx.z;
    const int c0 = zz * CPZ;
    const int nc = min(CPZ, NCHUNK - c0);
    float* C = Cpart + (size_t)zz * M * N;
    const int lr = lane >> 2, lc = lane & 3;

    float acc[2][4][4];
    #pragma unroll
    for (int i = 0; i < 2; ++i)
        #pragma unroll
        for (int j = 0; j < 4; ++j)
            #pragma unroll
            for (int k = 0; k < 4; ++k) acc[i][j][k] = 0.f;

    #pragma unroll
    for (int t = 0; t < 2; ++t) {
        if (t < nc) load_stage_f64(A, Bt, M, N, K, rowBase, (c0 + t) << 5, sbase + t * STAGEB, tid);
        asm volatile("cp.async.commit_group;" ::: "memory");
    }

    float rsacc = 0.f;
    const int rrow = tid >> 1;
    const int rhalf = tid & 1;

    for (int t = 0; t < nc; ++t) {
        if (t + 2 < nc)
            load_stage_f64(A, Bt, M, N, K, rowBase, (c0 + t + 2) << 5,
                           sbase + ((t + 2) % STAGES) * STAGEB, tid);
        asm volatile("cp.async.commit_group;" ::: "memory");
        asm volatile("cp.async.wait_group 2;" ::: "memory");
        __syncthreads();

        const float* As = sm + (t % STAGES) * (STAGEB / 4);
        const float* Bs = As + 128 * (ROWB / 4);

        {
            const float* pr = As + rrow * 36 + rhalf * 16;
            float s = 0.f;
            #pragma unroll
            for (int j = 0; j < 16; ++j) s += pr[j];
            rsacc += s;
        }

        #pragma unroll
        for (int kb = 0; kb < 32; kb += 16) {
            uint32_t ah[2][4], al[2][4], bh[4][2], bl[4][2];
            #pragma unroll
            for (int mi = 0; mi < 2; ++mi) {
                const float* p = As + (warpM * 32 + mi * 16 + lr) * 36 + kb + 2 * lc;
                float2 v00 = *(const float2*)(p);
                float2 v10 = *(const float2*)(p + 8 * 36);
                float2 v01 = *(const float2*)(p + 8);
                float2 v11 = *(const float2*)(p + 8 * 36 + 8);
                bfsplit2(v00.x, v00.y, ah[mi][0], al[mi][0]);
                bfsplit2(v10.x, v10.y, ah[mi][1], al[mi][1]);
                bfsplit2(v01.x, v01.y, ah[mi][2], al[mi][2]);
                bfsplit2(v11.x, v11.y, ah[mi][3], al[mi][3]);
            }
            #pragma unroll
            for (int ni = 0; ni < 4; ++ni) {
                const float* p = Bs + (warpN * 32 + ni * 8 + lr) * 36 + kb + 2 * lc;
                float2 w0 = *(const float2*)(p);
                float2 w1 = *(const float2*)(p + 8);
                bfsplit2(w0.x, w0.y, bh[ni][0], bl[ni][0]);
                bfsplit2(w1.x, w1.y, bh[ni][1], bl[ni][1]);
            }
            #pragma unroll
            for (int mi = 0; mi < 2; ++mi)
                #pragma unroll
                for (int ni = 0; ni < 4; ++ni) {
                    mma_bf16(acc[mi][ni], ah[mi], bh[ni]);
                    mma_bf16(acc[mi][ni], ah[mi], bl[ni]);
                    mma_bf16(acc[mi][ni], al[mi], bh[ni]);
                }
        }
        __syncthreads();
    }

    rsacc += __shfl_xor_sync(0xffffffffu, rsacc, 1);
    if (rhalf == 0) {
        int gr = rowBase + rrow;
        if (gr < M) atomicAdd(&rowsum[gr], rsacc);
    }

    #pragma unroll
    for (int mi = 0; mi < 2; ++mi) {
        int r0 = rowBase + warpM * 32 + mi * 16 + lr;
        #pragma unroll
        for (int ni = 0; ni < 4; ++ni) {
            int gc = warpN * 32 + ni * 8 + lc * 2;
            if (gc >= N) continue;
            if (r0 < M)
                *(float2*)&C[(size_t)r0 * N + gc] = make_float2(acc[mi][ni][0], acc[mi][ni][1]);
            if (r0 + 8 < M)
                *(float2*)&C[(size_t)(r0 + 8) * N + gc] = make_float2(acc[mi][ni][2], acc[mi][ni][3]);
        }
    }
}

__global__ void reduce4_kernel(const float* __restrict__ part, float* __restrict__ outp, int n) {
    int i = blockIdx.x * blockDim.x + threadIdx.x;
    if (i < n) outp[i] = part[i] + part[i + n] + part[i + 2 * n] + part[i + 3 * n];
}

// ============================ small kernels ============================
__global__ void relu_kernel(const float* __restrict__ in, float* __restrict__ out, int n) {
    int i = blockIdx.x * blockDim.x + threadIdx.x;
    if (i < n) out[i] = fmaxf(in[i], 0.f);
}

__global__ void l2norm_split_f16(const float* __restrict__ in,
                                 fp16* __restrict__ oh, fp16* __restrict__ ol, int n) {
    int warp = (blockIdx.x * blockDim.x + threadIdx.x) >> 5;
    int lane = threadIdx.x & 31;
    if (warp >= n) return;
    float v0 = in[warp * 64 + lane];
    float v1 = in[warp * 64 + 32 + lane];
    float ss = v0 * v0 + v1 * v1;
    #pragma unroll
    for (int o = 16; o > 0; o >>= 1) ss += __shfl_xor_sync(0xffffffffu, ss, o);
    float inv = 1.f / fmaxf(sqrtf(ss), 1e-12f);
    fp16 h, l;
    splitf16(v0 * inv, h, l); oh[warp * 64 + lane] = h; ol[warp * 64 + lane] = l;
    splitf16(v1 * inv, h, l); oh[warp * 64 + 32 + lane] = h; ol[warp * 64 + 32 + lane] = l;
}

__global__ void g2_kernel(const float* __restrict__ vsum, const float* __restrict__ rowsum,
                          float* __restrict__ g2, int n) {
    int warp = (blockIdx.x * blockDim.x + threadIdx.x) >> 5;
    int lane = threadIdx.x & 31;
    if (warp >= n) return;
    float inv_rs = 1.f / rowsum[warp];
    float v0 = vsum[warp * 64 + lane] * inv_rs;
    float v1 = vsum[warp * 64 + 32 + lane] * inv_rs;
    float ss = v0 * v0 + v1 * v1;
    #pragma unroll
    for (int o = 16; o > 0; o >>= 1) ss += __shfl_xor_sync(0xffffffffu, ss, o);
    float inv = 1.f / fmaxf(sqrtf(ss), 1e-12f);
    v0 *= inv; v1 *= inv;
    g2[warp * 64 + lane] = 1.f / (1.f + expf(-v0));
    g2[warp * 64 + 32 + lane] = 1.f / (1.f + expf(-v1));
}

__global__ void disc_kernel(const float* __restrict__ emb1, const float* __restrict__ emb3,
                            const float* __restrict__ g2, const float* __restrict__ W,
                            const float* __restrict__ bptr, float* __restrict__ ret) {
    __shared__ float g2s[64];
    __shared__ float r1[64], r2[64];
    int r = blockIdx.x, t = threadIdx.x;
    g2s[t] = g2[r * 64 + t];
    __syncthreads();
    float u = 0.f;
    #pragma unroll
    for (int e = 0; e < 64; ++e) u += W[t * 64 + e] * g2s[e];
    r1[t] = emb1[r * 64 + t] * u;
    r2[t] = emb3[r * 64 + t] * u;
    __syncthreads();
    for (int s = 32; s > 0; s >>= 1) {
        if (t < s) { r1[t] += r1[t + s]; r2[t] += r2[t + s]; }
        __syncthreads();
    }
    if (t == 0) {
        float b = bptr[0];
        ret[r * 2 + 0] = r1[0] + b;
        ret[r * 2 + 1] = r2[0] + b;
    }
}

// ============================ host orchestration ============================
extern "C" void kernel_launch(void* const* d_in, const int* in_sizes, int n_in,
                              void* d_out, int out_size) {
    const float* feat     = (const float*)d_in[0];
    const float* feat_a   = (const float*)d_in[1];
    const float* feat_b   = (const float*)d_in[2];
    const int*   adj_rows = (const int*)  d_in[3];
    const int*   adj_cols = (const int*)  d_in[4];
    const float* adj_vals = (const float*)d_in[5];
    const float* graph_ng = (const float*)d_in[6];
    const float* W1       = (const float*)d_in[7];
    const float* W2       = (const float*)d_in[8];
    const float* Wd       = (const float*)d_in[9];
    const float* bd       = (const float*)d_in[10];
    const float* bn_gamma = (const float*)d_in[11];
    const float* bn_beta  = (const float*)d_in[12];
    const float* bn_mean  = (const float*)d_in[13];
    const float* bn_var   = (const float*)d_in[14];
    const float* Wpi      = (const float*)d_in[15];
    const float* bpi      = (const float*)d_in[16];
    const float* Wdisp    = (const float*)d_in[17];
    const float* bdisp    = (const float*)d_in[18];
    const float* Wmean    = (const float*)d_in[19];
    const float* bmean    = (const float*)d_in[20];
    const float* disc_W   = (const float*)d_in[21];
    const float* disc_b   = (const float*)d_in[22];

    float* out = (float*)d_out;
    float* o_z1   = out;
    float* o_pi   = out + 1920000;
    float* o_z3   = out + 1280000;
    float* o_rec  = out + 91920000;
    float* o_ret  = out + 191920000;

    float *s2, *emb1, *emb3, *vsum4, *vsum, *g2, *rowsum, *cval, *emb1t;
    int *cnt, *cur, *rowptr, *ccol;
    fp16 *s1, *fAh, *fAl, *w1t, *xdh, *znh, *znl, *wzt;
    bf16 *hh, *hl, *z1h, *z1l, *w2th, *w2tl, *wdth, *wdtl;

    cudaGetSymbolAddress((void**)&s1, g_s1);
    cudaGetSymbolAddress((void**)&s2, g_s2);
    cudaGetSymbolAddress((void**)&emb1, g_emb1);
    cudaGetSymbolAddress((void**)&emb3, g_emb3);
    cudaGetSymbolAddress((void**)&vsum4, g_vsum4);
    cudaGetSymbolAddress((void**)&vsum, g_vsum);
    cudaGetSymbolAddress((void**)&g2,   g_g2);
    cudaGetSymbolAddress((void**)&rowsum, g_rowsum);
    cudaGetSymbolAddress((void**)&emb1t,  g_emb1t);
    cudaGetSymbolAddress((void**)&cnt,    g_cnt);
    cudaGetSymbolAddress((void**)&cur,    g_cur);
    cudaGetSymbolAddress((void**)&rowptr, g_rowptr);
    cudaGetSymbolAddress((void**)&ccol,   g_ccol);
    cudaGetSymbolAddress((void**)&cval,   g_cval);
    cudaGetSymbolAddress((void**)&fAh, g_fA_h); cudaGetSymbolAddress((void**)&fAl, g_fA_l);
    cudaGetSymbolAddress((void**)&w1t, g_w1t);
    cudaGetSymbolAddress((void**)&hh,  g_h_h);  cudaGetSymbolAddress((void**)&hl,  g_h_l);
    cudaGetSymbolAddress((void**)&z1h, g_z1_h); cudaGetSymbolAddress((void**)&z1l, g_z1_l);
    cudaGetSymbolAddress((void**)&xdh, g_xd_h);
    cudaGetSymbolAddress((void**)&znh, g_zn_h); cudaGetSymbolAddress((void**)&znl, g_zn_l);
    cudaGetSymbolAddress((void**)&w2th, g_w2t_h); cudaGetSymbolAddress((void**)&w2tl, g_w2t_l);
    cudaGetSymbolAddress((void**)&wdth, g_wdt_h); cudaGetSymbolAddress((void**)&wdtl, g_wdt_l);
    cudaGetSymbolAddress((void**)&wzt,  g_wzt);

    // ---- CSR build ----
    cudaMemsetAsync(cnt, 0, NN * sizeof(int));
    count_kernel<<<cdiv(NE, 256), 256>>>(adj_rows, cnt, NE);
    scan_kernel<<<1, 1024>>>(cnt, rowptr, NN);
    cudaMemsetAsync(cur, 0, NN * sizeof(int));
    scatter_kernel<<<cdiv(NE, 256), 256>>>(adj_rows, adj_cols, adj_vals,
                                           rowptr, cur, ccol, cval, NE);

    // ---- weight transpose + split / quant ----
    dim3 tb(32, 8);
    transpose_quant_f16<<<dim3(cdiv(H1D, 32), cdiv(FIN, 32)), tb>>>(W1, w1t, FIN, H1D, FIN);
    transpose_split_kernel<<<dim3(cdiv(H2D, 32), cdiv(H1D, 32)), tb>>>(W2, w2th, w2tl, H1D, H2D, LDH);
    transpose_split_kernel<<<dim3(cdiv(H1D, 32), cdiv(H2D, 32)), tb>>>(Wd, wdth, wdtl, H2D, H1D, H2D);
    const long long WZS = (long long)FIN * LDH;
    transpose_quant_f16<<<dim3(cdiv(FIN, 32), cdiv(H1D, 32)), tb>>>(Wpi,   wzt,           H1D, FIN, LDH);
    transpose_quant_f16<<<dim3(cdiv(FIN, 32), cdiv(H1D, 32)), tb>>>(Wdisp, wzt + WZS,     H1D, FIN, LDH);
    transpose_quant_f16<<<dim3(cdiv(FIN, 32), cdiv(H1D, 32)), tb>>>(Wmean, wzt + 2 * WZS, H1D, FIN, LDH);

    // ---- feats split upfront (fp16 2-plane, exact) ----
    const long long FAS = (long long)NN * FIN;
    split_f16_kernel<<<cdiv(NN * FIN / 4, 256), 256>>>(feat,   fAh,           fAl,           NN * FIN / 4);
    split_f16_kernel<<<cdiv(NN * FIN / 4, 256), 256>>>(feat_a, fAh + FAS,     fAl + FAS,     NN * FIN / 4);
    split_f16_kernel<<<cdiv(NN * FIN / 4, 256), 256>>>(feat_b, fAh + 2 * FAS, fAl + 2 * FAS, NN * FIN / 4);

    // ---- batched 3x GCN encode: GEMM1 fp16 2-term -> fp16 s1, GEMM2 bf16 3-term ----
    launch_t2<128, 7, true>(fAh, fAl, w1t, nullptr, s1, NN, H1D, FIN,
                            FIN, FIN, H1D, 3, FAS, 0, (long long)NN * H1D);
    agg_split_kernel<<<dim3(cdiv(H1D, 128), NN, 3), 128>>>(s1, hh, hl, rowptr, ccol, cval,
                                                           H1D, LDH, (long long)NN * H1D, (long long)NN * LDH);
    launch_tb<64, 0>(hh, hl, w2th, w2tl, s2, nullptr, NN, H2D, H1D,
                     LDH, LDH, H2D, 3, (long long)NN * LDH, 0, (long long)NN * H2D);
    agg_kernel<<<dim3(1, NN, 3), 128>>>(s2, out, rowptr, ccol, cval, H2D, 0,
                                        (long long)NN * H2D, 640000LL);   // writes z1, z2, z3

    relu_kernel<<<cdiv(NN * H2D, 256), 256>>>(o_z1, emb1, NN * H2D);
    relu_kernel<<<cdiv(NN * H2D, 256), 256>>>(o_z3, emb3, NN * H2D);
    split_bf_kernel<<<cdiv(NN * H2D / 4, 256), 256>>>(o_z1, z1h, z1l, NN * H2D / 4);
    l2norm_split_f16<<<cdiv(NN, 8), 256>>>(o_z1, znh, znl, NN);

    // ---- ZINB decoder: hidden (bf16 3-term, writes single fp16 plane), then 1-term fp16 ----
    launch_tb<128, 1>(z1h, z1l, wdth, wdtl, nullptr, xdh, NN, H1D, H2D,
                      H2D, H2D, LDH, 1, 0, 0, 0, bd, bn_gamma, bn_beta, bn_mean, bn_var);
    launch_t2<128, 6, false>(xdh, nullptr, wzt, o_pi, nullptr, NN, FIN, H1D,
                             LDH, LDH, FIN, 3, 0, WZS, 30000000LL, bpi, bdisp, bmean);

    // ---- adjacency reconstruction: sigmoid(zn @ zn^T), fp16 2-term ----
    launch_t2<128, 5, true>(znh, znl, znh, o_rec, nullptr, NN, NN, H2D,
                            H2D, H2D, NN, 1, 0, 0, 0);

    // ---- readout (split-K GEMM + fused rowsum) + discriminator ----
    cudaMemsetAsync(rowsum, 0, NN * sizeof(float));
    transpose_kernel<<<dim3(cdiv(H2D, 32), cdiv(NN, 32)), tb>>>(emb1, emb1t, NN, H2D);
    {
        constexpr int SMEMSZ = STAGES * 192 * ROWB;
        cudaFuncSetAttribute(tgemm64sk, cudaFuncAttributeMaxDynamicSharedMemorySize, SMEMSZ);
        dim3 grid(1, cdiv(NN, 128), 4);
        tgemm64sk<<<grid, 256, SMEMSZ>>>(graph_ng, emb1t, vsum4, rowsum, NN, H2D, NN);
    }
    reduce4_kernel<<<cdiv(NN * H2D, 256), 256>>>(vsum4, vsum, NN * H2D);
    g2_kernel<<<cdiv(NN, 8), 256>>>(vsum, rowsum, g2, NN);
    disc_kernel<<<NN, 64>>>(emb1, emb3, g2, disc_W, disc_b, o_ret);
}